// round 7
// baseline (speedup 1.0000x reference)
#include <cuda_runtime.h>
#include <math.h>

#define BATCH 2048
#define DD 784
#define ZZ 32
#define HH 512
#define F_LOG2PI 1.8378770664093453f

// ---------------- scratch (device globals; no allocation allowed) ----------------
__device__ __align__(256) float g_G[HH * HH];
__device__ __align__(256) float g_c[HH];
__device__ __align__(256) float g_u[BATCH * HH];
__device__ __align__(256) float g_h1[BATCH * HH];
__device__ __align__(256) float g_h2[BATCH * HH];
__device__ __align__(256) float g_v[BATCH * HH];
__device__ __align__(256) float g_mu[BATCH * ZZ];
__device__ __align__(256) float g_z[BATCH * ZZ];
__device__ __align__(256) float g_T1[(size_t)BATCH * HH * ZZ];   // reused as px_mu at end
__device__ __align__(256) float g_GA2[(size_t)BATCH * HH * ZZ];
__device__ __align__(256) float g_perb[BATCH];

enum { EPI_NONE = 0, EPI_BIAS = 1, EPI_RELUB = 2, EPI_VEPI = 3 };

// ---------------- generic 64x64x16 tiled GEMM, 256 threads, 4x4 microtile --------
// C[M,N] = op(A) @ op(B). TA: A stored [K,M]. TB: B stored [N,K]. M%64==0, K%16==0.
// EPI_BIAS: +P0[n]; EPI_RELUB: relu(acc+P0[n]); EPI_VEPI: C = P0[m,n] - acc - P1[n].
template <bool TA, bool TB, int EPI>
__global__ __launch_bounds__(256)
void gemm64(const float* __restrict__ A, const float* __restrict__ B,
            float* __restrict__ C, int M, int N, int K,
            const float* __restrict__ P0, const float* __restrict__ P1)
{
    __shared__ __align__(16) float As[16][64];
    __shared__ __align__(16) float Bs[16][64];
    const int t = threadIdx.x;
    const int rowBase = blockIdx.y * 64;
    const int colBase = blockIdx.x * 64;
    const int ty = t >> 4, tx = t & 15;

    float acc[4][4];
#pragma unroll
    for (int i = 0; i < 4; ++i)
#pragma unroll
        for (int j = 0; j < 4; ++j) acc[i][j] = 0.f;

    for (int k0 = 0; k0 < K; k0 += 16) {
        if (!TA) {
            int r = t >> 2;
            int k4 = (t & 3) << 2;
            float4 v = *(const float4*)(A + (size_t)(rowBase + r) * K + k0 + k4);
            As[k4 + 0][r] = v.x; As[k4 + 1][r] = v.y;
            As[k4 + 2][r] = v.z; As[k4 + 3][r] = v.w;
        } else {
            int k = t >> 4;
            int m0 = (t & 15) << 2;
            *(float4*)(&As[k][m0]) =
                *(const float4*)(A + (size_t)(k0 + k) * M + rowBase + m0);
        }
        if (!TB) {
            int k = t >> 4;
            int n0 = (t & 15) << 2;
            int gn = colBase + n0;
            float4 v = make_float4(0.f, 0.f, 0.f, 0.f);
            if (gn < N) v = *(const float4*)(B + (size_t)(k0 + k) * N + gn);
            *(float4*)(&Bs[k][n0]) = v;
        } else {
            int n = t >> 2;
            int k4 = (t & 3) << 2;
            int gn = colBase + n;
            float4 v = make_float4(0.f, 0.f, 0.f, 0.f);
            if (gn < N) v = *(const float4*)(B + (size_t)gn * K + k0 + k4);
            Bs[k4 + 0][n] = v.x; Bs[k4 + 1][n] = v.y;
            Bs[k4 + 2][n] = v.z; Bs[k4 + 3][n] = v.w;
        }
        __syncthreads();
#pragma unroll
        for (int k = 0; k < 16; ++k) {
            float4 a = *(const float4*)(&As[k][ty << 2]);
            float4 b = *(const float4*)(&Bs[k][tx << 2]);
            float av[4] = {a.x, a.y, a.z, a.w};
            float bv[4] = {b.x, b.y, b.z, b.w};
#pragma unroll
            for (int i = 0; i < 4; ++i)
#pragma unroll
                for (int j = 0; j < 4; ++j)
                    acc[i][j] = fmaf(av[i], bv[j], acc[i][j]);
        }
        __syncthreads();
    }
#pragma unroll
    for (int i = 0; i < 4; ++i) {
        int m = rowBase + (ty << 2) + i;
#pragma unroll
        for (int j = 0; j < 4; ++j) {
            int n = colBase + (tx << 2) + j;
            if (n < N) {
                float vv = acc[i][j];
                if (EPI == EPI_BIAS) vv += P0[n];
                else if (EPI == EPI_RELUB) vv = fmaxf(vv + P0[n], 0.f);
                else if (EPI == EPI_VEPI) vv = P0[(size_t)m * N + n] - vv - P1[n];
                C[(size_t)m * N + n] = vv;
            }
        }
    }
}

// ---------------- masked batched GEMM (the hot kernel) ---------------------------
// Out[b,i,z] = sum_j A[i,j] * (Hm[b,j]>0) * Bsrc[b*bstride + j*32 + z]
// A: [512,512] shared. Column tile 64 = 2 batches x 32 z. grid = (B/2, 512/64).
__global__ __launch_bounds__(256)
void masked_gemm(const float* __restrict__ A, const float* __restrict__ Bsrc,
                 const float* __restrict__ Hm, float* __restrict__ Out, int bstride)
{
    __shared__ __align__(16) float As[16][64];
    __shared__ __align__(16) float Bs[16][64];
    const int t = threadIdx.x;
    const int rowBase = blockIdx.y * 64;
    const int b0 = blockIdx.x * 2;
    const int ty = t >> 4, tx = t & 15;

    float acc[4][4];
#pragma unroll
    for (int i = 0; i < 4; ++i)
#pragma unroll
        for (int j = 0; j < 4; ++j) acc[i][j] = 0.f;

    const int lk = t >> 4;          // 0..15 (k within tile)
    const int lc0 = (t & 15) << 2;  // 0..60 (col within tile, stays in one batch)
    const int lb = b0 + (lc0 >> 5);
    const int lz = lc0 & 31;
    const float* Bb = Bsrc + (size_t)lb * bstride;
    const float* Hb = Hm + (size_t)lb * HH;

    const int ar = t >> 2;
    const int ak4 = (t & 3) << 2;
    const float* Arow = A + (size_t)(rowBase + ar) * HH + ak4;

    for (int k0 = 0; k0 < HH; k0 += 16) {
        {
            float4 v = *(const float4*)(Arow + k0);
            As[ak4 + 0][ar] = v.x; As[ak4 + 1][ar] = v.y;
            As[ak4 + 2][ar] = v.z; As[ak4 + 3][ar] = v.w;
        }
        {
            int kk = k0 + lk;
            float4 v = *(const float4*)(Bb + (size_t)kk * ZZ + lz);
            float m = (Hb[kk] > 0.f) ? 1.f : 0.f;
            v.x *= m; v.y *= m; v.z *= m; v.w *= m;
            *(float4*)(&Bs[lk][lc0]) = v;
        }
        __syncthreads();
#pragma unroll
        for (int k = 0; k < 16; ++k) {
            float4 a = *(const float4*)(&As[k][ty << 2]);
            float4 b = *(const float4*)(&Bs[k][tx << 2]);
            float av[4] = {a.x, a.y, a.z, a.w};
            float bv[4] = {b.x, b.y, b.z, b.w};
#pragma unroll
            for (int i = 0; i < 4; ++i)
#pragma unroll
                for (int j = 0; j < 4; ++j)
                    acc[i][j] = fmaf(av[i], bv[j], acc[i][j]);
        }
        __syncthreads();
    }
    const int cb = b0 + ((tx << 2) >> 5);
    const int cz = (tx << 2) & 31;
    float* Ob = Out + (size_t)cb * (HH * ZZ);
#pragma unroll
    for (int i = 0; i < 4; ++i) {
        int row = rowBase + (ty << 2) + i;
        float4 o = make_float4(acc[i][0], acc[i][1], acc[i][2], acc[i][3]);
        *(float4*)(Ob + (size_t)row * ZZ + cz) = o;
    }
}

// ---------------- per-batch iteration update -------------------------------------
__global__ __launch_bounds__(256)
void iter_update(const float* __restrict__ dlv, float alpha)
{
    const int b = blockIdx.x;
    const int t = threadIdx.x;
    __shared__ __align__(16) float A2s[64][32];
    __shared__ __align__(16) float G2s[64][32];
    __shared__ float vs[64];
    __shared__ float Msh[32][33];
    __shared__ float Csh[32][33];
    __shared__ float r1[32], muS[32], rhs[32];

    const float* T1b = g_T1 + (size_t)b * (HH * ZZ);
    const float* G2b = g_GA2 + (size_t)b * (HH * ZZ);
    const float* h2b = g_h2 + (size_t)b * HH;
    const float* vb  = g_v + (size_t)b * HH;

    float accM[4] = {0.f, 0.f, 0.f, 0.f};
    float accR = 0.f;

    for (int j0 = 0; j0 < HH; j0 += 64) {
        __syncthreads();
        for (int e = t * 4; e < 2048; e += 1024) {
            int j = e >> 5, z = e & 31;
            float m = (h2b[j0 + j] > 0.f) ? 1.f : 0.f;
            float4 a = *(const float4*)(T1b + (size_t)(j0 + j) * ZZ + z);
            a.x *= m; a.y *= m; a.z *= m; a.w *= m;
            *(float4*)(&A2s[j][z]) = a;
            *(float4*)(&G2s[j][z]) = *(const float4*)(G2b + (size_t)(j0 + j) * ZZ + z);
        }
        if (t < 64) vs[t] = vb[j0 + t];
        __syncthreads();
#pragma unroll
        for (int q = 0; q < 4; ++q) {
            int z1 = (t >> 5) + (q << 3);
            int z2 = t & 31;
            float s = 0.f;
#pragma unroll 16
            for (int j = 0; j < 64; ++j)
                s = fmaf(A2s[j][z1], G2s[j][z2], s);
            accM[q] += s;
        }
        if (t < 32) {
            float s = 0.f;
#pragma unroll 16
            for (int j = 0; j < 64; ++j) s = fmaf(A2s[j][t], vs[j], s);
            accR += s;
        }
    }
    __syncthreads();
    {
        int z2 = t & 31;
        int r0 = t >> 5;
#pragma unroll
        for (int q = 0; q < 4; ++q) Msh[r0 + (q << 3)][z2] = accM[q];
    }
    if (t < 32) {
        r1[t]  = accR;
        muS[t] = g_mu[b * ZZ + t];
    }
    __syncthreads();

    if (t < 32) {
        const int lane = t;
        const float vinv = expf(-dlv[0]);
        float s = 0.f;
#pragma unroll
        for (int c = 0; c < 32; ++c) {
            Csh[lane][c] = vinv * Msh[lane][c] + ((lane == c) ? 1.f : 0.f);
            s = fmaf(Msh[lane][c], muS[c], s);
        }
        rhs[lane] = vinv * (r1[lane] + s);
        __syncwarp();
        // Cholesky (lower, in place)
        for (int k = 0; k < 32; ++k) {
            if (lane == k) Csh[k][k] = sqrtf(Csh[k][k]);
            __syncwarp();
            float dk = Csh[k][k];
            if (lane > k) Csh[lane][k] /= dk;
            __syncwarp();
            if (lane > k) {
                float lk = Csh[lane][k];
                for (int c = k + 1; c <= lane; ++c)
                    Csh[lane][c] -= lk * Csh[c][k];
            }
            __syncwarp();
        }
        // forward: L y = rhs
        for (int k = 0; k < 32; ++k) {
            if (lane == k) rhs[k] /= Csh[k][k];
            __syncwarp();
            if (lane > k) rhs[lane] -= Csh[lane][k] * rhs[k];
            __syncwarp();
        }
        // backward: L^T x = y
        for (int k = 31; k >= 0; --k) {
            if (lane == k) rhs[k] /= Csh[k][k];
            __syncwarp();
            if (lane < k) rhs[lane] -= Csh[k][lane] * rhs[k];
            __syncwarp();
        }
        g_mu[b * ZZ + lane] = (1.f - alpha) * muS[lane] + alpha * rhs[lane];
    }
}

// ---------------- final per-batch: cov -> inv -> chol -> z, p_z - q_z ------------
__global__ __launch_bounds__(256)
void final_stats(const float* __restrict__ eps, const float* __restrict__ dlv)
{
    const int b = blockIdx.x;
    const int t = threadIdx.x;
    __shared__ __align__(16) float A2s[64][32];
    __shared__ __align__(16) float G2s[64][32];
    __shared__ float Msh[32][33];
    __shared__ float Csh[32][33];
    __shared__ float Xsh[32][33];
    __shared__ float Vsh[32][33];
    __shared__ float muS[32], epsS[32], dzS[32];

    const float* T1b = g_T1 + (size_t)b * (HH * ZZ);
    const float* G2b = g_GA2 + (size_t)b * (HH * ZZ);
    const float* h2b = g_h2 + (size_t)b * HH;

    float accM[4] = {0.f, 0.f, 0.f, 0.f};
    for (int j0 = 0; j0 < HH; j0 += 64) {
        __syncthreads();
        for (int e = t * 4; e < 2048; e += 1024) {
            int j = e >> 5, z = e & 31;
            float m = (h2b[j0 + j] > 0.f) ? 1.f : 0.f;
            float4 a = *(const float4*)(T1b + (size_t)(j0 + j) * ZZ + z);
            a.x *= m; a.y *= m; a.z *= m; a.w *= m;
            *(float4*)(&A2s[j][z]) = a;
            *(float4*)(&G2s[j][z]) = *(const float4*)(G2b + (size_t)(j0 + j) * ZZ + z);
        }
        __syncthreads();
#pragma unroll
        for (int q = 0; q < 4; ++q) {
            int z1 = (t >> 5) + (q << 3);
            int z2 = t & 31;
            float s = 0.f;
#pragma unroll 16
            for (int j = 0; j < 64; ++j)
                s = fmaf(A2s[j][z1], G2s[j][z2], s);
            accM[q] += s;
        }
    }
    __syncthreads();
    {
        int z2 = t & 31;
        int r0 = t >> 5;
#pragma unroll
        for (int q = 0; q < 4; ++q) Msh[r0 + (q << 3)][z2] = accM[q];
    }
    if (t < 32) {
        muS[t]  = g_mu[b * ZZ + t];
        epsS[t] = eps[b * ZZ + t];
    }
    __syncthreads();

    if (t < 32) {
        const int i = t;
        const float vinv = expf(-dlv[0]);
#pragma unroll
        for (int c = 0; c < 32; ++c)
            Csh[i][c] = vinv * Msh[i][c] + ((i == c) ? 1.f : 0.f);
        __syncwarp();
        // C = chol(cov), lower
        for (int k = 0; k < 32; ++k) {
            if (i == k) Csh[k][k] = sqrtf(Csh[k][k]);
            __syncwarp();
            float dk = Csh[k][k];
            if (i > k) Csh[i][k] /= dk;
            __syncwarp();
            if (i > k) {
                float lk = Csh[i][k];
                for (int c = k + 1; c <= i; ++c)
                    Csh[i][c] -= lk * Csh[c][k];
            }
            __syncwarp();
        }
        // X = C^{-1} (lower); lane i owns column i
        for (int r = 0; r < 32; ++r) Xsh[r][i] = 0.f;
        __syncwarp();
        Xsh[i][i] = 1.f / Csh[i][i];
        for (int r = i + 1; r < 32; ++r) {
            float s = 0.f;
            for (int k = i; k < r; ++k) s = fmaf(Csh[r][k], Xsh[k][i], s);
            Xsh[r][i] = -s / Csh[r][r];
        }
        __syncwarp();
        // cov_inv = X^T X
        for (int c = 0; c < 32; ++c) {
            float s = 0.f;
            int km = (i > c) ? i : c;
            for (int k = km; k < 32; ++k) s = fmaf(Xsh[k][i], Xsh[k][c], s);
            Vsh[i][c] = s;
        }
        __syncwarp();
        // L = chol(cov_inv), lower, in place in Vsh
        for (int k = 0; k < 32; ++k) {
            if (i == k) Vsh[k][k] = sqrtf(Vsh[k][k]);
            __syncwarp();
            float dk = Vsh[k][k];
            if (i > k) Vsh[i][k] /= dk;
            __syncwarp();
            if (i > k) {
                float lk = Vsh[i][k];
                for (int c = k + 1; c <= i; ++c)
                    Vsh[i][c] -= lk * Vsh[c][k];
            }
            __syncwarp();
        }
        // z = mu + L eps
        float dz = 0.f;
        for (int c = 0; c <= i; ++c) dz = fmaf(Vsh[i][c], epsS[c], dz);
        float zi = muS[i] + dz;
        g_z[b * ZZ + i] = zi;
        dzS[i] = dz;
        __syncwarp();
        // quad = dz^T cov dz, cov = vinv*M + I
        float cd = 0.f;
#pragma unroll
        for (int c = 0; c < 32; ++c)
            cd = fmaf(vinv * Msh[i][c] + ((i == c) ? 1.f : 0.f), dzS[c], cd);
        float qpart = dzS[i] * cd;
        // per-lane contribution of (p_z - q_z)
        float contrib = 0.5f * (F_LOG2PI + zi * zi)          // p_z
                      + 0.5f * F_LOG2PI + logf(Vsh[i][i])    // -q_z (log-det part)
                      + 0.5f * qpart;                        // -q_z (quad part)
#pragma unroll
        for (int o = 16; o > 0; o >>= 1)
            contrib += __shfl_down_sync(0xffffffffu, contrib, o);
        if (i == 0) g_perb[b] = contrib;
    }
}

// ---------------- p_x reduction + final mean -------------------------------------
__global__ __launch_bounds__(256)
void px_reduce(const float* __restrict__ x, const float* __restrict__ pxmu,
               const float* __restrict__ dlv)
{
    const int b = blockIdx.x;
    const int t = threadIdx.x;
    const float dl = dlv[0];
    const float vinv = expf(-dl);
    float s = 0.f;
    for (int d = t; d < DD; d += 256) {
        float r = x[(size_t)b * DD + d] - pxmu[(size_t)b * DD + d];
        s += F_LOG2PI + dl + r * r * vinv;
    }
    __shared__ float sh[256];
    sh[t] = s; __syncthreads();
    for (int o = 128; o > 0; o >>= 1) {
        if (t < o) sh[t] += sh[t + o];
        __syncthreads();
    }
    if (t == 0) g_perb[b] += 0.5f * sh[0];
}

__global__ __launch_bounds__(256)
void final_reduce(float* __restrict__ out)
{
    const int t = threadIdx.x;
    float s = 0.f;
    for (int i = t; i < BATCH; i += 256) s += g_perb[i];
    __shared__ float sh[256];
    sh[t] = s; __syncthreads();
    for (int o = 128; o > 0; o >>= 1) {
        if (t < o) sh[t] += sh[t + o];
        __syncthreads();
    }
    if (t == 0) out[0] = -sh[0] / (float)BATCH;
}

__global__ void compute_c(const float* __restrict__ Wmu, const float* __restrict__ bmu,
                          float* __restrict__ c)
{
    int j = blockIdx.x * 256 + threadIdx.x;
    if (j < HH) {
        float s = 0.f;
        for (int d = 0; d < DD; ++d) s = fmaf(Wmu[(size_t)d * HH + j], bmu[d], s);
        c[j] = s;
    }
}

// ---------------- host orchestration ---------------------------------------------
extern "C" void kernel_launch(void* const* d_in, const int* in_sizes, int n_in,
                              void* d_out, int out_size)
{
    const float* x    = (const float*)d_in[0];
    const float* eps  = (const float*)d_in[1];
    const float* We1  = (const float*)d_in[2];
    const float* be1  = (const float*)d_in[3];
    const float* We2  = (const float*)d_in[4];
    const float* be2  = (const float*)d_in[5];
    const float* Wmue = (const float*)d_in[6];
    const float* bmue = (const float*)d_in[7];
    const float* Wd1  = (const float*)d_in[8];
    const float* bd1  = (const float*)d_in[9];
    const float* Wd2  = (const float*)d_in[10];
    const float* bd2  = (const float*)d_in[11];
    const float* Wmu  = (const float*)d_in[12];
    const float* bmu  = (const float*)d_in[13];
    const float* dlv  = (const float*)d_in[14];
    float* out = (float*)d_out;

    void *pG, *pc, *pu, *ph1, *ph2, *pv, *pmu, *pz, *pT1, *pGA2;
    cudaGetSymbolAddress(&pG, g_G);     cudaGetSymbolAddress(&pc, g_c);
    cudaGetSymbolAddress(&pu, g_u);     cudaGetSymbolAddress(&ph1, g_h1);
    cudaGetSymbolAddress(&ph2, g_h2);   cudaGetSymbolAddress(&pv, g_v);
    cudaGetSymbolAddress(&pmu, g_mu);   cudaGetSymbolAddress(&pz, g_z);
    cudaGetSymbolAddress(&pT1, g_T1);   cudaGetSymbolAddress(&pGA2, g_GA2);
    float *G = (float*)pG, *c = (float*)pc, *u = (float*)pu;
    float *h1 = (float*)ph1, *h2 = (float*)ph2, *v = (float*)pv;
    float *mu = (float*)pmu, *z = (float*)pz, *T1 = (float*)pT1, *GA2 = (float*)pGA2;

    dim3 blk(256);

    // G = Wmu^T Wmu  [512,512], K=784
    gemm64<true, false, EPI_NONE><<<dim3(8, 8), blk>>>(Wmu, Wmu, G, HH, HH, DD, nullptr, nullptr);
    // c = Wmu^T bmu
    compute_c<<<2, 256>>>(Wmu, bmu, c);
    // u = x @ Wmu  [2048,512], K=784
    gemm64<false, false, EPI_NONE><<<dim3(8, 32), blk>>>(x, Wmu, u, BATCH, HH, DD, nullptr, nullptr);
    // encoder
    gemm64<false, true, EPI_RELUB><<<dim3(8, 32), blk>>>(x, We1, h1, BATCH, HH, DD, be1, nullptr);
    gemm64<false, true, EPI_RELUB><<<dim3(8, 32), blk>>>(h1, We2, h2, BATCH, HH, HH, be2, nullptr);
    gemm64<false, true, EPI_BIAS><<<dim3(1, 32), blk>>>(h2, Wmue, mu, BATCH, ZZ, HH, bmue, nullptr);

    for (int i = 0; i < 10; ++i) {
        gemm64<false, true, EPI_RELUB><<<dim3(8, 32), blk>>>(mu, Wd1, h1, BATCH, HH, ZZ, bd1, nullptr);
        gemm64<false, true, EPI_RELUB><<<dim3(8, 32), blk>>>(h1, Wd2, h2, BATCH, HH, HH, bd2, nullptr);
        gemm64<false, false, EPI_VEPI><<<dim3(8, 32), blk>>>(h2, G, v, BATCH, HH, HH, u, c);
        masked_gemm<<<dim3(BATCH / 2, 8), blk>>>(Wd2, Wd1, h1, T1, 0);
        masked_gemm<<<dim3(BATCH / 2, 8), blk>>>(G, T1, h2, GA2, HH * ZZ);
        iter_update<<<BATCH, 256>>>(dlv, 0.5f / (1.0f + (float)i));
    }

    // final Laplace covariance at converged mu
    gemm64<false, true, EPI_RELUB><<<dim3(8, 32), blk>>>(mu, Wd1, h1, BATCH, HH, ZZ, bd1, nullptr);
    gemm64<false, true, EPI_RELUB><<<dim3(8, 32), blk>>>(h1, Wd2, h2, BATCH, HH, HH, bd2, nullptr);
    masked_gemm<<<dim3(BATCH / 2, 8), blk>>>(Wd2, Wd1, h1, T1, 0);
    masked_gemm<<<dim3(BATCH / 2, 8), blk>>>(G, T1, h2, GA2, HH * ZZ);
    final_stats<<<BATCH, 256>>>(eps, dlv);

    // decoder at z: px_mu into T1 (reused)
    gemm64<false, true, EPI_RELUB><<<dim3(8, 32), blk>>>(z, Wd1, h1, BATCH, HH, ZZ, bd1, nullptr);
    gemm64<false, true, EPI_RELUB><<<dim3(8, 32), blk>>>(h1, Wd2, h2, BATCH, HH, HH, bd2, nullptr);
    gemm64<false, true, EPI_BIAS><<<dim3(13, 32), blk>>>(h2, Wmu, T1, BATCH, DD, HH, bmu, nullptr);

    px_reduce<<<BATCH, 256>>>(x, T1, dlv);
    final_reduce<<<1, 256>>>(out);
}

// round 8
// speedup vs baseline: 1.2319x; 1.2319x over previous
#include <cuda_runtime.h>
#include <math.h>

#define BATCH 2048
#define DD 784
#define ZZ 32
#define HH 512
#define F_LOG2PI 1.8378770664093453f

// ---------------- scratch (device globals; no allocation allowed) ----------------
__device__ __align__(256) float g_G[HH * HH];
__device__ __align__(256) float g_c[HH];
__device__ __align__(256) float g_u[BATCH * HH];
__device__ __align__(256) float g_h1[BATCH * HH];
__device__ __align__(256) float g_h2[BATCH * HH];
__device__ __align__(256) float g_v[BATCH * HH];
__device__ __align__(256) float g_mu[BATCH * ZZ];
__device__ __align__(256) float g_z[BATCH * ZZ];
__device__ __align__(256) float g_T1[(size_t)BATCH * HH * ZZ];   // reused as px_mu at end
__device__ __align__(256) float g_GA2[(size_t)BATCH * HH * ZZ];
__device__ __align__(256) float g_perb[BATCH];

enum { EPI_NONE = 0, EPI_BIAS = 1, EPI_RELUB = 2, EPI_VEPI = 3 };

// ---------------- packed f32x2 helpers (FFMA2) -----------------------------------
__device__ __forceinline__ unsigned long long pack2(float x) {
    unsigned long long d;
    asm("mov.b64 %0, {%1, %1};" : "=l"(d) : "f"(x));
    return d;
}
__device__ __forceinline__ void pack_from4(const float4& v,
                                           unsigned long long& p0,
                                           unsigned long long& p1) {
    asm("mov.b64 %0, {%1, %2};" : "=l"(p0) : "f"(v.x), "f"(v.y));
    asm("mov.b64 %0, {%1, %2};" : "=l"(p1) : "f"(v.z), "f"(v.w));
}
__device__ __forceinline__ void ffma2(unsigned long long& acc,
                                      unsigned long long a, unsigned long long b) {
    asm("fma.rn.f32x2 %0, %1, %2, %0;" : "+l"(acc) : "l"(a), "l"(b));
}
__device__ __forceinline__ float2 unpack2(unsigned long long d) {
    float lo, hi;
    asm("mov.b64 {%0, %1}, %2;" : "=f"(lo), "=f"(hi) : "l"(d));
    return make_float2(lo, hi);
}

// ---------------- generic 64x64x16 tiled GEMM, f32x2 inner -----------------------
// C[M,N] = op(A) @ op(B). TA: A stored [K,M]. TB: B stored [N,K]. M%64==0, K%16==0.
// EPI_BIAS: +P0[n]; EPI_RELUB: relu(acc+P0[n]); EPI_VEPI: C = P0[m,n] - acc - P1[n].
template <bool TA, bool TB, int EPI>
__global__ __launch_bounds__(256)
void gemm64(const float* __restrict__ A, const float* __restrict__ B,
            float* __restrict__ C, int M, int N, int K,
            const float* __restrict__ P0, const float* __restrict__ P1)
{
    __shared__ __align__(16) float As[16][64];
    __shared__ __align__(16) float Bs[16][64];
    const int t = threadIdx.x;
    const int rowBase = blockIdx.y * 64;
    const int colBase = blockIdx.x * 64;
    const int ty = t >> 4, tx = t & 15;

    unsigned long long acc[4][2] = {};

    for (int k0 = 0; k0 < K; k0 += 16) {
        if (!TA) {
            int r = t >> 2;
            int k4 = (t & 3) << 2;
            float4 v = *(const float4*)(A + (size_t)(rowBase + r) * K + k0 + k4);
            As[k4 + 0][r] = v.x; As[k4 + 1][r] = v.y;
            As[k4 + 2][r] = v.z; As[k4 + 3][r] = v.w;
        } else {
            int k = t >> 4;
            int m0 = (t & 15) << 2;
            *(float4*)(&As[k][m0]) =
                *(const float4*)(A + (size_t)(k0 + k) * M + rowBase + m0);
        }
        if (!TB) {
            int k = t >> 4;
            int n0 = (t & 15) << 2;
            int gn = colBase + n0;
            float4 v = make_float4(0.f, 0.f, 0.f, 0.f);
            if (gn < N) v = *(const float4*)(B + (size_t)(k0 + k) * N + gn);
            *(float4*)(&Bs[k][n0]) = v;
        } else {
            int n = t >> 2;
            int k4 = (t & 3) << 2;
            int gn = colBase + n;
            float4 v = make_float4(0.f, 0.f, 0.f, 0.f);
            if (gn < N) v = *(const float4*)(B + (size_t)gn * K + k0 + k4);
            Bs[k4 + 0][n] = v.x; Bs[k4 + 1][n] = v.y;
            Bs[k4 + 2][n] = v.z; Bs[k4 + 3][n] = v.w;
        }
        __syncthreads();
#pragma unroll
        for (int k = 0; k < 16; ++k) {
            float4 a = *(const float4*)(&As[k][ty << 2]);
            float4 b = *(const float4*)(&Bs[k][tx << 2]);
            unsigned long long bp[2];
            pack_from4(b, bp[0], bp[1]);
            unsigned long long ap[4];
            ap[0] = pack2(a.x); ap[1] = pack2(a.y);
            ap[2] = pack2(a.z); ap[3] = pack2(a.w);
#pragma unroll
            for (int i = 0; i < 4; ++i)
#pragma unroll
                for (int j = 0; j < 2; ++j)
                    ffma2(acc[i][j], ap[i], bp[j]);
        }
        __syncthreads();
    }
#pragma unroll
    for (int i = 0; i < 4; ++i) {
        int m = rowBase + (ty << 2) + i;
        float2 e0 = unpack2(acc[i][0]);
        float2 e1 = unpack2(acc[i][1]);
        float vals[4] = {e0.x, e0.y, e1.x, e1.y};
#pragma unroll
        for (int j = 0; j < 4; ++j) {
            int n = colBase + (tx << 2) + j;
            if (n < N) {
                float vv = vals[j];
                if (EPI == EPI_BIAS) vv += P0[n];
                else if (EPI == EPI_RELUB) vv = fmaxf(vv + P0[n], 0.f);
                else if (EPI == EPI_VEPI) vv = P0[(size_t)m * N + n] - vv - P1[n];
                C[(size_t)m * N + n] = vv;
            }
        }
    }
}

// ---------------- masked batched GEMM (the hot kernel), 128x128, FFMA2 -----------
// Out[b,i,z] = sum_j A[i,j] * (Hm[b,j]>0) * Bsrc[b*bstride + j*32 + z]
// A: [512,512] shared. Col tile 128 = 4 batches x 32 z. grid = (B/4, 512/128).
__global__ __launch_bounds__(256, 2)
void masked_gemm2(const float* __restrict__ A, const float* __restrict__ Bsrc,
                  const float* __restrict__ Hm, float* __restrict__ Out, int bstride)
{
    __shared__ __align__(16) float As[16][128];
    __shared__ __align__(16) float Bs[16][128];
    const int t = threadIdx.x;
    const int rowBase = blockIdx.y * 128;
    const int b0 = blockIdx.x * 4;
    const int ty = t >> 4;   // row group: 8 rows
    const int tx = t & 15;   // col group: 8 cols

    unsigned long long acc[8][4] = {};

    const int ar = t >> 2;            // 0..63 (+64 on second pass)
    const int ak4 = (t & 3) << 2;
    const int bk = t >> 5;            // 0..7 (+8 on second pass)
    const int bcol = (t & 31) << 2;   // 0..124, z-aligned 4
    const int bb = b0 + (bcol >> 5);
    const int bz = bcol & 31;
    const float* Bb = Bsrc + (size_t)bb * bstride;
    const float* Hb = Hm + (size_t)bb * HH;

    for (int k0 = 0; k0 < HH; k0 += 16) {
#pragma unroll
        for (int p = 0; p < 2; ++p) {
            int r = ar + (p << 6);
            float4 v = *(const float4*)(A + (size_t)(rowBase + r) * HH + k0 + ak4);
            As[ak4 + 0][r] = v.x; As[ak4 + 1][r] = v.y;
            As[ak4 + 2][r] = v.z; As[ak4 + 3][r] = v.w;
        }
#pragma unroll
        for (int p = 0; p < 2; ++p) {
            int k = bk + (p << 3);
            int kk = k0 + k;
            float4 v = *(const float4*)(Bb + (size_t)kk * ZZ + bz);
            float m = (Hb[kk] > 0.f) ? 1.f : 0.f;
            v.x *= m; v.y *= m; v.z *= m; v.w *= m;
            *(float4*)(&Bs[k][bcol]) = v;
        }
        __syncthreads();
#pragma unroll
        for (int k = 0; k < 16; ++k) {
            float4 a0  = *(const float4*)(&As[k][ty << 3]);
            float4 a1  = *(const float4*)(&As[k][(ty << 3) + 4]);
            float4 bv0 = *(const float4*)(&Bs[k][tx << 3]);
            float4 bv1 = *(const float4*)(&Bs[k][(tx << 3) + 4]);
            unsigned long long bp[4];
            pack_from4(bv0, bp[0], bp[1]);
            pack_from4(bv1, bp[2], bp[3]);
            unsigned long long ap[8];
            ap[0] = pack2(a0.x); ap[1] = pack2(a0.y);
            ap[2] = pack2(a0.z); ap[3] = pack2(a0.w);
            ap[4] = pack2(a1.x); ap[5] = pack2(a1.y);
            ap[6] = pack2(a1.z); ap[7] = pack2(a1.w);
#pragma unroll
            for (int i = 0; i < 8; ++i)
#pragma unroll
                for (int j = 0; j < 4; ++j)
                    ffma2(acc[i][j], ap[i], bp[j]);
        }
        __syncthreads();
    }
    const int cb = b0 + ((tx << 3) >> 5);
    const int cz = (tx << 3) & 31;
    float* Ob = Out + (size_t)cb * (HH * ZZ);
#pragma unroll
    for (int i = 0; i < 8; ++i) {
        int row = rowBase + (ty << 3) + i;
        float2 e0 = unpack2(acc[i][0]);
        float2 e1 = unpack2(acc[i][1]);
        float2 e2 = unpack2(acc[i][2]);
        float2 e3 = unpack2(acc[i][3]);
        *(float4*)(Ob + (size_t)row * ZZ + cz)     = make_float4(e0.x, e0.y, e1.x, e1.y);
        *(float4*)(Ob + (size_t)row * ZZ + cz + 4) = make_float4(e2.x, e2.y, e3.x, e3.y);
    }
}

// ---------------- per-batch iteration update -------------------------------------
__global__ __launch_bounds__(256)
void iter_update(const float* __restrict__ dlv, float alpha)
{
    const int b = blockIdx.x;
    const int t = threadIdx.x;
    __shared__ __align__(16) float A2s[64][32];
    __shared__ __align__(16) float G2s[64][32];
    __shared__ float vs[64];
    __shared__ float Msh[32][33];
    __shared__ float Csh[32][33];
    __shared__ float r1[32], muS[32], rhs[32];

    const float* T1b = g_T1 + (size_t)b * (HH * ZZ);
    const float* G2b = g_GA2 + (size_t)b * (HH * ZZ);
    const float* h2b = g_h2 + (size_t)b * HH;
    const float* vb  = g_v + (size_t)b * HH;

    float accM[4] = {0.f, 0.f, 0.f, 0.f};
    float accR = 0.f;

    for (int j0 = 0; j0 < HH; j0 += 64) {
        __syncthreads();
        for (int e = t * 4; e < 2048; e += 1024) {
            int j = e >> 5, z = e & 31;
            float m = (h2b[j0 + j] > 0.f) ? 1.f : 0.f;
            float4 a = *(const float4*)(T1b + (size_t)(j0 + j) * ZZ + z);
            a.x *= m; a.y *= m; a.z *= m; a.w *= m;
            *(float4*)(&A2s[j][z]) = a;
            *(float4*)(&G2s[j][z]) = *(const float4*)(G2b + (size_t)(j0 + j) * ZZ + z);
        }
        if (t < 64) vs[t] = vb[j0 + t];
        __syncthreads();
#pragma unroll
        for (int q = 0; q < 4; ++q) {
            int z1 = (t >> 5) + (q << 3);
            int z2 = t & 31;
            float s = 0.f;
#pragma unroll 16
            for (int j = 0; j < 64; ++j)
                s = fmaf(A2s[j][z1], G2s[j][z2], s);
            accM[q] += s;
        }
        if (t < 32) {
            float s = 0.f;
#pragma unroll 16
            for (int j = 0; j < 64; ++j) s = fmaf(A2s[j][t], vs[j], s);
            accR += s;
        }
    }
    __syncthreads();
    {
        int z2 = t & 31;
        int r0 = t >> 5;
#pragma unroll
        for (int q = 0; q < 4; ++q) Msh[r0 + (q << 3)][z2] = accM[q];
    }
    if (t < 32) {
        r1[t]  = accR;
        muS[t] = g_mu[b * ZZ + t];
    }
    __syncthreads();

    if (t < 32) {
        const int lane = t;
        const float vinv = expf(-dlv[0]);
        float s = 0.f;
#pragma unroll
        for (int c = 0; c < 32; ++c) {
            Csh[lane][c] = vinv * Msh[lane][c] + ((lane == c) ? 1.f : 0.f);
            s = fmaf(Msh[lane][c], muS[c], s);
        }
        rhs[lane] = vinv * (r1[lane] + s);
        __syncwarp();
        // Cholesky (lower, in place)
        for (int k = 0; k < 32; ++k) {
            if (lane == k) Csh[k][k] = sqrtf(Csh[k][k]);
            __syncwarp();
            float dk = Csh[k][k];
            if (lane > k) Csh[lane][k] /= dk;
            __syncwarp();
            if (lane > k) {
                float lk = Csh[lane][k];
                for (int c = k + 1; c <= lane; ++c)
                    Csh[lane][c] -= lk * Csh[c][k];
            }
            __syncwarp();
        }
        // forward: L y = rhs
        for (int k = 0; k < 32; ++k) {
            if (lane == k) rhs[k] /= Csh[k][k];
            __syncwarp();
            if (lane > k) rhs[lane] -= Csh[lane][k] * rhs[k];
            __syncwarp();
        }
        // backward: L^T x = y
        for (int k = 31; k >= 0; --k) {
            if (lane == k) rhs[k] /= Csh[k][k];
            __syncwarp();
            if (lane < k) rhs[lane] -= Csh[k][lane] * rhs[k];
            __syncwarp();
        }
        g_mu[b * ZZ + lane] = (1.f - alpha) * muS[lane] + alpha * rhs[lane];
    }
}

// ---------------- final per-batch: cov -> inv -> chol -> z, p_z - q_z ------------
__global__ __launch_bounds__(256)
void final_stats(const float* __restrict__ eps, const float* __restrict__ dlv)
{
    const int b = blockIdx.x;
    const int t = threadIdx.x;
    __shared__ __align__(16) float A2s[64][32];
    __shared__ __align__(16) float G2s[64][32];
    __shared__ float Msh[32][33];
    __shared__ float Csh[32][33];
    __shared__ float Xsh[32][33];
    __shared__ float Vsh[32][33];
    __shared__ float muS[32], epsS[32], dzS[32];

    const float* T1b = g_T1 + (size_t)b * (HH * ZZ);
    const float* G2b = g_GA2 + (size_t)b * (HH * ZZ);
    const float* h2b = g_h2 + (size_t)b * HH;

    float accM[4] = {0.f, 0.f, 0.f, 0.f};
    for (int j0 = 0; j0 < HH; j0 += 64) {
        __syncthreads();
        for (int e = t * 4; e < 2048; e += 1024) {
            int j = e >> 5, z = e & 31;
            float m = (h2b[j0 + j] > 0.f) ? 1.f : 0.f;
            float4 a = *(const float4*)(T1b + (size_t)(j0 + j) * ZZ + z);
            a.x *= m; a.y *= m; a.z *= m; a.w *= m;
            *(float4*)(&A2s[j][z]) = a;
            *(float4*)(&G2s[j][z]) = *(const float4*)(G2b + (size_t)(j0 + j) * ZZ + z);
        }
        __syncthreads();
#pragma unroll
        for (int q = 0; q < 4; ++q) {
            int z1 = (t >> 5) + (q << 3);
            int z2 = t & 31;
            float s = 0.f;
#pragma unroll 16
            for (int j = 0; j < 64; ++j)
                s = fmaf(A2s[j][z1], G2s[j][z2], s);
            accM[q] += s;
        }
    }
    __syncthreads();
    {
        int z2 = t & 31;
        int r0 = t >> 5;
#pragma unroll
        for (int q = 0; q < 4; ++q) Msh[r0 + (q << 3)][z2] = accM[q];
    }
    if (t < 32) {
        muS[t]  = g_mu[b * ZZ + t];
        epsS[t] = eps[b * ZZ + t];
    }
    __syncthreads();

    if (t < 32) {
        const int i = t;
        const float vinv = expf(-dlv[0]);
#pragma unroll
        for (int c = 0; c < 32; ++c)
            Csh[i][c] = vinv * Msh[i][c] + ((i == c) ? 1.f : 0.f);
        __syncwarp();
        // C = chol(cov), lower
        for (int k = 0; k < 32; ++k) {
            if (i == k) Csh[k][k] = sqrtf(Csh[k][k]);
            __syncwarp();
            float dk = Csh[k][k];
            if (i > k) Csh[i][k] /= dk;
            __syncwarp();
            if (i > k) {
                float lk = Csh[i][k];
                for (int c = k + 1; c <= i; ++c)
                    Csh[i][c] -= lk * Csh[c][k];
            }
            __syncwarp();
        }
        // X = C^{-1} (lower); lane i owns column i
        for (int r = 0; r < 32; ++r) Xsh[r][i] = 0.f;
        __syncwarp();
        Xsh[i][i] = 1.f / Csh[i][i];
        for (int r = i + 1; r < 32; ++r) {
            float s = 0.f;
            for (int k = i; k < r; ++k) s = fmaf(Csh[r][k], Xsh[k][i], s);
            Xsh[r][i] = -s / Csh[r][r];
        }
        __syncwarp();
        // cov_inv = X^T X
        for (int c = 0; c < 32; ++c) {
            float s = 0.f;
            int km = (i > c) ? i : c;
            for (int k = km; k < 32; ++k) s = fmaf(Xsh[k][i], Xsh[k][c], s);
            Vsh[i][c] = s;
        }
        __syncwarp();
        // L = chol(cov_inv), lower, in place in Vsh
        for (int k = 0; k < 32; ++k) {
            if (i == k) Vsh[k][k] = sqrtf(Vsh[k][k]);
            __syncwarp();
            float dk = Vsh[k][k];
            if (i > k) Vsh[i][k] /= dk;
            __syncwarp();
            if (i > k) {
                float lk = Vsh[i][k];
                for (int c = k + 1; c <= i; ++c)
                    Vsh[i][c] -= lk * Vsh[c][k];
            }
            __syncwarp();
        }
        // z = mu + L eps
        float dz = 0.f;
        for (int c = 0; c <= i; ++c) dz = fmaf(Vsh[i][c], epsS[c], dz);
        float zi = muS[i] + dz;
        g_z[b * ZZ + i] = zi;
        dzS[i] = dz;
        __syncwarp();
        // quad = dz^T cov dz, cov = vinv*M + I
        float cd = 0.f;
#pragma unroll
        for (int c = 0; c < 32; ++c)
            cd = fmaf(vinv * Msh[i][c] + ((i == c) ? 1.f : 0.f), dzS[c], cd);
        float qpart = dzS[i] * cd;
        float contrib = 0.5f * (F_LOG2PI + zi * zi)
                      + 0.5f * F_LOG2PI + logf(Vsh[i][i])
                      + 0.5f * qpart;
#pragma unroll
        for (int o = 16; o > 0; o >>= 1)
            contrib += __shfl_down_sync(0xffffffffu, contrib, o);
        if (i == 0) g_perb[b] = contrib;
    }
}

// ---------------- p_x reduction + final mean -------------------------------------
__global__ __launch_bounds__(256)
void px_reduce(const float* __restrict__ x, const float* __restrict__ pxmu,
               const float* __restrict__ dlv)
{
    const int b = blockIdx.x;
    const int t = threadIdx.x;
    const float dl = dlv[0];
    const float vinv = expf(-dl);
    float s = 0.f;
    for (int d = t; d < DD; d += 256) {
        float r = x[(size_t)b * DD + d] - pxmu[(size_t)b * DD + d];
        s += F_LOG2PI + dl + r * r * vinv;
    }
    __shared__ float sh[256];
    sh[t] = s; __syncthreads();
    for (int o = 128; o > 0; o >>= 1) {
        if (t < o) sh[t] += sh[t + o];
        __syncthreads();
    }
    if (t == 0) g_perb[b] += 0.5f * sh[0];
}

__global__ __launch_bounds__(256)
void final_reduce(float* __restrict__ out)
{
    const int t = threadIdx.x;
    float s = 0.f;
    for (int i = t; i < BATCH; i += 256) s += g_perb[i];
    __shared__ float sh[256];
    sh[t] = s; __syncthreads();
    for (int o = 128; o > 0; o >>= 1) {
        if (t < o) sh[t] += sh[t + o];
        __syncthreads();
    }
    if (t == 0) out[0] = -sh[0] / (float)BATCH;
}

__global__ void compute_c(const float* __restrict__ Wmu, const float* __restrict__ bmu,
                          float* __restrict__ c)
{
    int j = blockIdx.x * 256 + threadIdx.x;
    if (j < HH) {
        float s = 0.f;
        for (int d = 0; d < DD; ++d) s = fmaf(Wmu[(size_t)d * HH + j], bmu[d], s);
        c[j] = s;
    }
}

// ---------------- host orchestration ---------------------------------------------
extern "C" void kernel_launch(void* const* d_in, const int* in_sizes, int n_in,
                              void* d_out, int out_size)
{
    const float* x    = (const float*)d_in[0];
    const float* eps  = (const float*)d_in[1];
    const float* We1  = (const float*)d_in[2];
    const float* be1  = (const float*)d_in[3];
    const float* We2  = (const float*)d_in[4];
    const float* be2  = (const float*)d_in[5];
    const float* Wmue = (const float*)d_in[6];
    const float* bmue = (const float*)d_in[7];
    const float* Wd1  = (const float*)d_in[8];
    const float* bd1  = (const float*)d_in[9];
    const float* Wd2  = (const float*)d_in[10];
    const float* bd2  = (const float*)d_in[11];
    const float* Wmu  = (const float*)d_in[12];
    const float* bmu  = (const float*)d_in[13];
    const float* dlv  = (const float*)d_in[14];
    float* out = (float*)d_out;

    void *pG, *pc, *pu, *ph1, *ph2, *pv, *pmu, *pz, *pT1, *pGA2;
    cudaGetSymbolAddress(&pG, g_G);     cudaGetSymbolAddress(&pc, g_c);
    cudaGetSymbolAddress(&pu, g_u);     cudaGetSymbolAddress(&ph1, g_h1);
    cudaGetSymbolAddress(&ph2, g_h2);   cudaGetSymbolAddress(&pv, g_v);
    cudaGetSymbolAddress(&pmu, g_mu);   cudaGetSymbolAddress(&pz, g_z);
    cudaGetSymbolAddress(&pT1, g_T1);   cudaGetSymbolAddress(&pGA2, g_GA2);
    float *G = (float*)pG, *c = (float*)pc, *u = (float*)pu;
    float *h1 = (float*)ph1, *h2 = (float*)ph2, *v = (float*)pv;
    float *mu = (float*)pmu, *z = (float*)pz, *T1 = (float*)pT1, *GA2 = (float*)pGA2;

    dim3 blk(256);
    dim3 mgrid(BATCH / 4, HH / 128);

    // G = Wmu^T Wmu  [512,512], K=784
    gemm64<true, false, EPI_NONE><<<dim3(8, 8), blk>>>(Wmu, Wmu, G, HH, HH, DD, nullptr, nullptr);
    // c = Wmu^T bmu
    compute_c<<<2, 256>>>(Wmu, bmu, c);
    // u = x @ Wmu  [2048,512], K=784
    gemm64<false, false, EPI_NONE><<<dim3(8, 32), blk>>>(x, Wmu, u, BATCH, HH, DD, nullptr, nullptr);
    // encoder
    gemm64<false, true, EPI_RELUB><<<dim3(8, 32), blk>>>(x, We1, h1, BATCH, HH, DD, be1, nullptr);
    gemm64<false, true, EPI_RELUB><<<dim3(8, 32), blk>>>(h1, We2, h2, BATCH, HH, HH, be2, nullptr);
    gemm64<false, true, EPI_BIAS><<<dim3(1, 32), blk>>>(h2, Wmue, mu, BATCH, ZZ, HH, bmue, nullptr);

    for (int i = 0; i < 10; ++i) {
        gemm64<false, true, EPI_RELUB><<<dim3(8, 32), blk>>>(mu, Wd1, h1, BATCH, HH, ZZ, bd1, nullptr);
        gemm64<false, true, EPI_RELUB><<<dim3(8, 32), blk>>>(h1, Wd2, h2, BATCH, HH, HH, bd2, nullptr);
        gemm64<false, false, EPI_VEPI><<<dim3(8, 32), blk>>>(h2, G, v, BATCH, HH, HH, u, c);
        masked_gemm2<<<mgrid, blk>>>(Wd2, Wd1, h1, T1, 0);
        masked_gemm2<<<mgrid, blk>>>(G, T1, h2, GA2, HH * ZZ);
        iter_update<<<BATCH, 256>>>(dlv, 0.5f / (1.0f + (float)i));
    }

    // final Laplace covariance at converged mu
    gemm64<false, true, EPI_RELUB><<<dim3(8, 32), blk>>>(mu, Wd1, h1, BATCH, HH, ZZ, bd1, nullptr);
    gemm64<false, true, EPI_RELUB><<<dim3(8, 32), blk>>>(h1, Wd2, h2, BATCH, HH, HH, bd2, nullptr);
    masked_gemm2<<<mgrid, blk>>>(Wd2, Wd1, h1, T1, 0);
    masked_gemm2<<<mgrid, blk>>>(G, T1, h2, GA2, HH * ZZ);
    final_stats<<<BATCH, 256>>>(eps, dlv);

    // decoder at z: px_mu into T1 (reused)
    gemm64<false, true, EPI_RELUB><<<dim3(8, 32), blk>>>(z, Wd1, h1, BATCH, HH, ZZ, bd1, nullptr);
    gemm64<false, true, EPI_RELUB><<<dim3(8, 32), blk>>>(h1, Wd2, h2, BATCH, HH, HH, bd2, nullptr);
    gemm64<false, true, EPI_BIAS><<<dim3(13, 32), blk>>>(h2, Wmu, T1, BATCH, DD, HH, bmu, nullptr);

    px_reduce<<<BATCH, 256>>>(x, T1, dlv);
    final_reduce<<<1, 256>>>(out);
}

// round 13
// speedup vs baseline: 2.3122x; 1.8770x over previous
#include <cuda_runtime.h>
#include <math.h>
#include <stdint.h>

#define BATCH 2048
#define DD 784
#define ZZ 32
#define HH 512
#define F_LOG2PI 1.8378770664093453f

// ---------------- scratch (device globals; no allocation allowed) ----------------
__device__ __align__(256) float g_G[HH * HH];
__device__ __align__(256) float g_c[HH];
__device__ __align__(256) float g_u[BATCH * HH];
__device__ __align__(256) float g_h1[BATCH * HH];
__device__ __align__(256) float g_h2[BATCH * HH];
__device__ __align__(256) float g_v[BATCH * HH];
__device__ __align__(256) float g_mu[BATCH * ZZ];
__device__ __align__(256) float g_z[BATCH * ZZ];
__device__ __align__(256) float g_T1[(size_t)BATCH * HH * ZZ];   // reused as px_mu at end
__device__ __align__(256) float g_GA2[(size_t)BATCH * HH * ZZ];
__device__ __align__(256) float g_perb[BATCH];

enum { EPI_NONE = 0, EPI_BIAS = 1, EPI_RELUB = 2, EPI_VEPI = 3 };

// ---------------- packed f32x2 helpers (FFMA2) -----------------------------------
__device__ __forceinline__ unsigned long long pack2(float x) {
    unsigned long long d;
    asm("mov.b64 %0, {%1, %1};" : "=l"(d) : "f"(x));
    return d;
}
__device__ __forceinline__ void pack_from4(const float4& v,
                                           unsigned long long& p0,
                                           unsigned long long& p1) {
    asm("mov.b64 %0, {%1, %2};" : "=l"(p0) : "f"(v.x), "f"(v.y));
    asm("mov.b64 %0, {%1, %2};" : "=l"(p1) : "f"(v.z), "f"(v.w));
}
__device__ __forceinline__ void ffma2(unsigned long long& acc,
                                      unsigned long long a, unsigned long long b) {
    asm("fma.rn.f32x2 %0, %1, %2, %0;" : "+l"(acc) : "l"(a), "l"(b));
}
__device__ __forceinline__ float2 unpack2(unsigned long long d) {
    float lo, hi;
    asm("mov.b64 {%0, %1}, %2;" : "=f"(lo), "=f"(hi) : "l"(d));
    return make_float2(lo, hi);
}

// ---------------- tf32 helpers ----------------------------------------------------
__device__ __forceinline__ float tf32r(float f) {
    uint32_t r;
    asm("cvt.rna.tf32.f32 %0, %1;" : "=r"(r) : "f"(f));
    return __uint_as_float(r);
}
__device__ __forceinline__ void mma_tf32_16x8x8(float* c, const uint32_t* a,
                                                const uint32_t* b) {
    asm volatile(
        "mma.sync.aligned.m16n8k8.row.col.f32.tf32.tf32.f32 "
        "{%0,%1,%2,%3}, {%4,%5,%6,%7}, {%8,%9}, {%0,%1,%2,%3};"
        : "+f"(c[0]), "+f"(c[1]), "+f"(c[2]), "+f"(c[3])
        : "r"(a[0]), "r"(a[1]), "r"(a[2]), "r"(a[3]), "r"(b[0]), "r"(b[1]));
}

// ---------------- masked batched GEMM via mma.sync tf32 (the hot kernel) ---------
// Out[b,i,z] = sum_j A[i,j] * (Hm[b,j]>0) * Bsrc[b*bstride + j*32 + z]
// CTA: 128 A-rows x 4 batches. 8 warps; warp w: batch (w>>1), m-half (w&1)*64.
// K in 32 chunks of 16, double-buffered smem. Fragment LDS strides 136/40 floats
// (both == 8 mod 32) -> conflict-free quarter-group gathers.
__global__ __launch_bounds__(256, 2)
void masked_mma(const float* __restrict__ A, const float* __restrict__ Bsrc,
                const float* __restrict__ Hm, float* __restrict__ Out, int bstride)
{
    __shared__ float As[2][16][136];
    __shared__ float Bs[2][4][16][40];

    const int t = threadIdx.x;
    const int w = t >> 5;
    const int lane = t & 31;
    const int rowBase = blockIdx.y * 128;
    const int b0 = blockIdx.x * 4;
    const int q = w >> 1;           // batch within CTA
    const int mh = (w & 1) * 64;    // m-half within 128-row tile

    float acc[4][4][4];
#pragma unroll
    for (int mt = 0; mt < 4; ++mt)
#pragma unroll
        for (int nt = 0; nt < 4; ++nt)
#pragma unroll
            for (int e = 0; e < 4; ++e) acc[mt][nt][e] = 0.f;

    const int g = lane >> 2;    // group row (0..7)
    const int kt = lane & 3;    // k within quad

    // ---- chunk loader ----
    auto load_chunk = [&](int c, int nb) {
        const int k0 = c * 16;
#pragma unroll
        for (int p = 0; p < 2; ++p) {
            int id = t + 256 * p;
            int m = id >> 2, kg = (id & 3) << 2;
            float4 v = *(const float4*)(A + (size_t)(rowBase + m) * HH + k0 + kg);
            As[nb][kg + 0][m] = tf32r(v.x);
            As[nb][kg + 1][m] = tf32r(v.y);
            As[nb][kg + 2][m] = tf32r(v.z);
            As[nb][kg + 3][m] = tf32r(v.w);
        }
#pragma unroll
        for (int p = 0; p < 2; ++p) {
            int id = t + 256 * p;
            int q2 = id >> 7, rem = id & 127;
            int k = rem >> 3, z4 = (rem & 7) << 2;
            const float* Bb = Bsrc + (size_t)(b0 + q2) * bstride;
            float4 v = *(const float4*)(Bb + (size_t)(k0 + k) * ZZ + z4);
            float msk = (Hm[(size_t)(b0 + q2) * HH + k0 + k] > 0.f) ? 1.f : 0.f;
            Bs[nb][q2][k][z4 + 0] = tf32r(v.x * msk);
            Bs[nb][q2][k][z4 + 1] = tf32r(v.y * msk);
            Bs[nb][q2][k][z4 + 2] = tf32r(v.z * msk);
            Bs[nb][q2][k][z4 + 3] = tf32r(v.w * msk);
        }
    };

    load_chunk(0, 0);
    __syncthreads();

    for (int c = 0; c < 32; ++c) {
        const int buf = c & 1;
        if (c < 31) load_chunk(c + 1, buf ^ 1);

#pragma unroll
        for (int ks = 0; ks < 2; ++ks) {
            const int kb = ks * 8;
            uint32_t af[4][4];
#pragma unroll
            for (int mt = 0; mt < 4; ++mt) {
                int m0 = mh + mt * 16;
                af[mt][0] = __float_as_uint(As[buf][kb + kt][m0 + g]);
                af[mt][1] = __float_as_uint(As[buf][kb + kt][m0 + 8 + g]);
                af[mt][2] = __float_as_uint(As[buf][kb + 4 + kt][m0 + g]);
                af[mt][3] = __float_as_uint(As[buf][kb + 4 + kt][m0 + 8 + g]);
            }
            uint32_t bf[4][2];
#pragma unroll
            for (int nt = 0; nt < 4; ++nt) {
                bf[nt][0] = __float_as_uint(Bs[buf][q][kb + kt][nt * 8 + g]);
                bf[nt][1] = __float_as_uint(Bs[buf][q][kb + 4 + kt][nt * 8 + g]);
            }
#pragma unroll
            for (int mt = 0; mt < 4; ++mt)
#pragma unroll
                for (int nt = 0; nt < 4; ++nt)
                    mma_tf32_16x8x8(acc[mt][nt], af[mt], bf[nt]);
        }
        __syncthreads();
    }

    // ---- epilogue: c0/c1 at (row=g, col=2*kt), c2/c3 at row=g+8 ----
    float* Ob = Out + (size_t)(b0 + q) * (HH * ZZ);
#pragma unroll
    for (int mt = 0; mt < 4; ++mt) {
        int row = rowBase + mh + mt * 16 + g;
#pragma unroll
        for (int nt = 0; nt < 4; ++nt) {
            int col = nt * 8 + kt * 2;
            *(float2*)(Ob + (size_t)row * ZZ + col) =
                make_float2(acc[mt][nt][0], acc[mt][nt][1]);
            *(float2*)(Ob + (size_t)(row + 8) * ZZ + col) =
                make_float2(acc[mt][nt][2], acc[mt][nt][3]);
        }
    }
}

// ---------------- generic 64x64x16 tiled GEMM, f32x2 inner -----------------------
template <bool TA, bool TB, int EPI>
__global__ __launch_bounds__(256)
void gemm64(const float* __restrict__ A, const float* __restrict__ B,
            float* __restrict__ C, int M, int N, int K,
            const float* __restrict__ P0, const float* __restrict__ P1)
{
    __shared__ __align__(16) float As[16][64];
    __shared__ __align__(16) float Bs[16][64];
    const int t = threadIdx.x;
    const int rowBase = blockIdx.y * 64;
    const int colBase = blockIdx.x * 64;
    const int ty = t >> 4, tx = t & 15;

    unsigned long long acc[4][2] = {};

    for (int k0 = 0; k0 < K; k0 += 16) {
        if (!TA) {
            int r = t >> 2;
            int k4 = (t & 3) << 2;
            float4 v = *(const float4*)(A + (size_t)(rowBase + r) * K + k0 + k4);
            As[k4 + 0][r] = v.x; As[k4 + 1][r] = v.y;
            As[k4 + 2][r] = v.z; As[k4 + 3][r] = v.w;
        } else {
            int k = t >> 4;
            int m0 = (t & 15) << 2;
            *(float4*)(&As[k][m0]) =
                *(const float4*)(A + (size_t)(k0 + k) * M + rowBase + m0);
        }
        if (!TB) {
            int k = t >> 4;
            int n0 = (t & 15) << 2;
            int gn = colBase + n0;
            float4 v = make_float4(0.f, 0.f, 0.f, 0.f);
            if (gn < N) v = *(const float4*)(B + (size_t)(k0 + k) * N + gn);
            *(float4*)(&Bs[k][n0]) = v;
        } else {
            int n = t >> 2;
            int k4 = (t & 3) << 2;
            int gn = colBase + n;
            float4 v = make_float4(0.f, 0.f, 0.f, 0.f);
            if (gn < N) v = *(const float4*)(B + (size_t)gn * K + k0 + k4);
            Bs[k4 + 0][n] = v.x; Bs[k4 + 1][n] = v.y;
            Bs[k4 + 2][n] = v.z; Bs[k4 + 3][n] = v.w;
        }
        __syncthreads();
#pragma unroll
        for (int k = 0; k < 16; ++k) {
            float4 a = *(const float4*)(&As[k][ty << 2]);
            float4 b = *(const float4*)(&Bs[k][tx << 2]);
            unsigned long long bp[2];
            pack_from4(b, bp[0], bp[1]);
            unsigned long long ap[4];
            ap[0] = pack2(a.x); ap[1] = pack2(a.y);
            ap[2] = pack2(a.z); ap[3] = pack2(a.w);
#pragma unroll
            for (int i = 0; i < 4; ++i)
#pragma unroll
                for (int j = 0; j < 2; ++j)
                    ffma2(acc[i][j], ap[i], bp[j]);
        }
        __syncthreads();
    }
#pragma unroll
    for (int i = 0; i < 4; ++i) {
        int m = rowBase + (ty << 2) + i;
        float2 e0 = unpack2(acc[i][0]);
        float2 e1 = unpack2(acc[i][1]);
        float vals[4] = {e0.x, e0.y, e1.x, e1.y};
#pragma unroll
        for (int j = 0; j < 4; ++j) {
            int n = colBase + (tx << 2) + j;
            if (n < N) {
                float vv = vals[j];
                if (EPI == EPI_BIAS) vv += P0[n];
                else if (EPI == EPI_RELUB) vv = fmaxf(vv + P0[n], 0.f);
                else if (EPI == EPI_VEPI) vv = P0[(size_t)m * N + n] - vv - P1[n];
                C[(size_t)m * N + n] = vv;
            }
        }
    }
}

// ---------------- per-batch iteration update -------------------------------------
__global__ __launch_bounds__(256)
void iter_update(const float* __restrict__ dlv, float alpha)
{
    const int b = blockIdx.x;
    const int t = threadIdx.x;
    __shared__ __align__(16) float A2s[64][32];
    __shared__ __align__(16) float G2s[64][32];
    __shared__ float vs[64];
    __shared__ float Msh[32][33];
    __shared__ float Csh[32][33];
    __shared__ float r1[32], muS[32], rhs[32];

    const float* T1b = g_T1 + (size_t)b * (HH * ZZ);
    const float* G2b = g_GA2 + (size_t)b * (HH * ZZ);
    const float* h2b = g_h2 + (size_t)b * HH;
    const float* vb  = g_v + (size_t)b * HH;

    float accM[4] = {0.f, 0.f, 0.f, 0.f};
    float accR = 0.f;

    for (int j0 = 0; j0 < HH; j0 += 64) {
        __syncthreads();
        for (int e = t * 4; e < 2048; e += 1024) {
            int j = e >> 5, z = e & 31;
            float m = (h2b[j0 + j] > 0.f) ? 1.f : 0.f;
            float4 a = *(const float4*)(T1b + (size_t)(j0 + j) * ZZ + z);
            a.x *= m; a.y *= m; a.z *= m; a.w *= m;
            *(float4*)(&A2s[j][z]) = a;
            *(float4*)(&G2s[j][z]) = *(const float4*)(G2b + (size_t)(j0 + j) * ZZ + z);
        }
        if (t < 64) vs[t] = vb[j0 + t];
        __syncthreads();
#pragma unroll
        for (int q = 0; q < 4; ++q) {
            int z1 = (t >> 5) + (q << 3);
            int z2 = t & 31;
            float s = 0.f;
#pragma unroll 16
            for (int j = 0; j < 64; ++j)
                s = fmaf(A2s[j][z1], G2s[j][z2], s);
            accM[q] += s;
        }
        if (t < 32) {
            float s = 0.f;
#pragma unroll 16
            for (int j = 0; j < 64; ++j) s = fmaf(A2s[j][t], vs[j], s);
            accR += s;
        }
    }
    __syncthreads();
    {
        int z2 = t & 31;
        int r0 = t >> 5;
#pragma unroll
        for (int q = 0; q < 4; ++q) Msh[r0 + (q << 3)][z2] = accM[q];
    }
    if (t < 32) {
        r1[t]  = accR;
        muS[t] = g_mu[b * ZZ + t];
    }
    __syncthreads();

    if (t < 32) {
        const int lane = t;
        const float vinv = expf(-dlv[0]);
        float s = 0.f;
#pragma unroll
        for (int c = 0; c < 32; ++c) {
            Csh[lane][c] = vinv * Msh[lane][c] + ((lane == c) ? 1.f : 0.f);
            s = fmaf(Msh[lane][c], muS[c], s);
        }
        rhs[lane] = vinv * (r1[lane] + s);
        __syncwarp();
        for (int k = 0; k < 32; ++k) {
            if (lane == k) Csh[k][k] = sqrtf(Csh[k][k]);
            __syncwarp();
            float dk = Csh[k][k];
            if (lane > k) Csh[lane][k] /= dk;
            __syncwarp();
            if (lane > k) {
                float lk = Csh[lane][k];
                for (int c = k + 1; c <= lane; ++c)
                    Csh[lane][c] -= lk * Csh[c][k];
            }
            __syncwarp();
        }
        for (int k = 0; k < 32; ++k) {
            if (lane == k) rhs[k] /= Csh[k][k];
            __syncwarp();
            if (lane > k) rhs[lane] -= Csh[lane][k] * rhs[k];
            __syncwarp();
        }
        for (int k = 31; k >= 0; --k) {
            if (lane == k) rhs[k] /= Csh[k][k];
            __syncwarp();
            if (lane < k) rhs[lane] -= Csh[k][lane] * rhs[k];
            __syncwarp();
        }
        g_mu[b * ZZ + lane] = (1.f - alpha) * muS[lane] + alpha * rhs[lane];
    }
}

// ---------------- final per-batch: cov -> inv -> chol -> z, p_z - q_z ------------
__global__ __launch_bounds__(256)
void final_stats(const float* __restrict__ eps, const float* __restrict__ dlv)
{
    const int b = blockIdx.x;
    const int t = threadIdx.x;
    __shared__ __align__(16) float A2s[64][32];
    __shared__ __align__(16) float G2s[64][32];
    __shared__ float Msh[32][33];
    __shared__ float Csh[32][33];
    __shared__ float Xsh[32][33];
    __shared__ float Vsh[32][33];
    __shared__ float muS[32], epsS[32], dzS[32];

    const float* T1b = g_T1 + (size_t)b * (HH * ZZ);
    const float* G2b = g_GA2 + (size_t)b * (HH * ZZ);
    const float* h2b = g_h2 + (size_t)b * HH;

    float accM[4] = {0.f, 0.f, 0.f, 0.f};
    for (int j0 = 0; j0 < HH; j0 += 64) {
        __syncthreads();
        for (int e = t * 4; e < 2048; e += 1024) {
            int j = e >> 5, z = e & 31;
            float m = (h2b[j0 + j] > 0.f) ? 1.f : 0.f;
            float4 a = *(const float4*)(T1b + (size_t)(j0 + j) * ZZ + z);
            a.x *= m; a.y *= m; a.z *= m; a.w *= m;
            *(float4*)(&A2s[j][z]) = a;
            *(float4*)(&G2s[j][z]) = *(const float4*)(G2b + (size_t)(j0 + j) * ZZ + z);
        }
        __syncthreads();
#pragma unroll
        for (int q = 0; q < 4; ++q) {
            int z1 = (t >> 5) + (q << 3);
            int z2 = t & 31;
            float s = 0.f;
#pragma unroll 16
            for (int j = 0; j < 64; ++j)
                s = fmaf(A2s[j][z1], G2s[j][z2], s);
            accM[q] += s;
        }
    }
    __syncthreads();
    {
        int z2 = t & 31;
        int r0 = t >> 5;
#pragma unroll
        for (int q = 0; q < 4; ++q) Msh[r0 + (q << 3)][z2] = accM[q];
    }
    if (t < 32) {
        muS[t]  = g_mu[b * ZZ + t];
        epsS[t] = eps[b * ZZ + t];
    }
    __syncthreads();

    if (t < 32) {
        const int i = t;
        const float vinv = expf(-dlv[0]);
#pragma unroll
        for (int c = 0; c < 32; ++c)
            Csh[i][c] = vinv * Msh[i][c] + ((i == c) ? 1.f : 0.f);
        __syncwarp();
        for (int k = 0; k < 32; ++k) {
            if (i == k) Csh[k][k] = sqrtf(Csh[k][k]);
            __syncwarp();
            float dk = Csh[k][k];
            if (i > k) Csh[i][k] /= dk;
            __syncwarp();
            if (i > k) {
                float lk = Csh[i][k];
                for (int c = k + 1; c <= i; ++c)
                    Csh[i][c] -= lk * Csh[c][k];
            }
            __syncwarp();
        }
        for (int r = 0; r < 32; ++r) Xsh[r][i] = 0.f;
        __syncwarp();
        Xsh[i][i] = 1.f / Csh[i][i];
        for (int r = i + 1; r < 32; ++r) {
            float s = 0.f;
            for (int k = i; k < r; ++k) s = fmaf(Csh[r][k], Xsh[k][i], s);
            Xsh[r][i] = -s / Csh[r][r];
        }
        __syncwarp();
        for (int c = 0; c < 32; ++c) {
            float s = 0.f;
            int km = (i > c) ? i : c;
            for (int k = km; k < 32; ++k) s = fmaf(Xsh[k][i], Xsh[k][c], s);
            Vsh[i][c] = s;
        }
        __syncwarp();
        for (int k = 0; k < 32; ++k) {
            if (i == k) Vsh[k][k] = sqrtf(Vsh[k][k]);
            __syncwarp();
            float dk = Vsh[k][k];
            if (i > k) Vsh[i][k] /= dk;
            __syncwarp();
            if (i > k) {
                float lk = Vsh[i][k];
                for (int c = k + 1; c <= i; ++c)
                    Vsh[i][c] -= lk * Vsh[c][k];
            }
            __syncwarp();
        }
        float dz = 0.f;
        for (int c = 0; c <= i; ++c) dz = fmaf(Vsh[i][c], epsS[c], dz);
        float zi = muS[i] + dz;
        g_z[b * ZZ + i] = zi;
        dzS[i] = dz;
        __syncwarp();
        float cd = 0.f;
#pragma unroll
        for (int c = 0; c < 32; ++c)
            cd = fmaf(vinv * Msh[i][c] + ((i == c) ? 1.f : 0.f), dzS[c], cd);
        float qpart = dzS[i] * cd;
        float contrib = 0.5f * (F_LOG2PI + zi * zi)
                      + 0.5f * F_LOG2PI + logf(Vsh[i][i])
                      + 0.5f * qpart;
#pragma unroll
        for (int o = 16; o > 0; o >>= 1)
            contrib += __shfl_down_sync(0xffffffffu, contrib, o);
        if (i == 0) g_perb[b] = contrib;
    }
}

// ---------------- p_x reduction + final mean -------------------------------------
__global__ __launch_bounds__(256)
void px_reduce(const float* __restrict__ x, const float* __restrict__ pxmu,
               const float* __restrict__ dlv)
{
    const int b = blockIdx.x;
    const int t = threadIdx.x;
    const float dl = dlv[0];
    const float vinv = expf(-dl);
    float s = 0.f;
    for (int d = t; d < DD; d += 256) {
        float r = x[(size_t)b * DD + d] - pxmu[(size_t)b * DD + d];
        s += F_LOG2PI + dl + r * r * vinv;
    }
    __shared__ float sh[256];
    sh[t] = s; __syncthreads();
    for (int o = 128; o > 0; o >>= 1) {
        if (t < o) sh[t] += sh[t + o];
        __syncthreads();
    }
    if (t == 0) g_perb[b] += 0.5f * sh[0];
}

__global__ __launch_bounds__(256)
void final_reduce(float* __restrict__ out)
{
    const int t = threadIdx.x;
    float s = 0.f;
    for (int i = t; i < BATCH; i += 256) s += g_perb[i];
    __shared__ float sh[256];
    sh[t] = s; __syncthreads();
    for (int o = 128; o > 0; o >>= 1) {
        if (t < o) sh[t] += sh[t + o];
        __syncthreads();
    }
    if (t == 0) out[0] = -sh[0] / (float)BATCH;
}

__global__ void compute_c(const float* __restrict__ Wmu, const float* __restrict__ bmu,
                          float* __restrict__ c)
{
    int j = blockIdx.x * 256 + threadIdx.x;
    if (j < HH) {
        float s = 0.f;
        for (int d = 0; d < DD; ++d) s = fmaf(Wmu[(size_t)d * HH + j], bmu[d], s);
        c[j] = s;
    }
}

// ---------------- host orchestration ---------------------------------------------
extern "C" void kernel_launch(void* const* d_in, const int* in_sizes, int n_in,
                              void* d_out, int out_size)
{
    const float* x    = (const float*)d_in[0];
    const float* eps  = (const float*)d_in[1];
    const float* We1  = (const float*)d_in[2];
    const float* be1  = (const float*)d_in[3];
    const float* We2  = (const float*)d_in[4];
    const float* be2  = (const float*)d_in[5];
    const float* Wmue = (const float*)d_in[6];
    const float* bmue = (const float*)d_in[7];
    const float* Wd1  = (const float*)d_in[8];
    const float* bd1  = (const float*)d_in[9];
    const float* Wd2  = (const float*)d_in[10];
    const float* bd2  = (const float*)d_in[11];
    const float* Wmu  = (const float*)d_in[12];
    const float* bmu  = (const float*)d_in[13];
    const float* dlv  = (const float*)d_in[14];
    float* out = (float*)d_out;

    void *pG, *pc, *pu, *ph1, *ph2, *pv, *pmu, *pz, *pT1, *pGA2;
    cudaGetSymbolAddress(&pG, g_G);     cudaGetSymbolAddress(&pc, g_c);
    cudaGetSymbolAddress(&pu, g_u);     cudaGetSymbolAddress(&ph1, g_h1);
    cudaGetSymbolAddress(&ph2, g_h2);   cudaGetSymbolAddress(&pv, g_v);
    cudaGetSymbolAddress(&pmu, g_mu);   cudaGetSymbolAddress(&pz, g_z);
    cudaGetSymbolAddress(&pT1, g_T1);   cudaGetSymbolAddress(&pGA2, g_GA2);
    float *G = (float*)pG, *c = (float*)pc, *u = (float*)pu;
    float *h1 = (float*)ph1, *h2 = (float*)ph2, *v = (float*)pv;
    float *mu = (float*)pmu, *z = (float*)pz, *T1 = (float*)pT1, *GA2 = (float*)pGA2;

    dim3 blk(256);
    dim3 tgrid(BATCH / 4, HH / 128);   // 512 x 4 CTAs

    gemm64<true, false, EPI_NONE><<<dim3(8, 8), blk>>>(Wmu, Wmu, G, HH, HH, DD, nullptr, nullptr);
    compute_c<<<2, 256>>>(Wmu, bmu, c);
    gemm64<false, false, EPI_NONE><<<dim3(8, 32), blk>>>(x, Wmu, u, BATCH, HH, DD, nullptr, nullptr);
    gemm64<false, true, EPI_RELUB><<<dim3(8, 32), blk>>>(x, We1, h1, BATCH, HH, DD, be1, nullptr);
    gemm64<false, true, EPI_RELUB><<<dim3(8, 32), blk>>>(h1, We2, h2, BATCH, HH, HH, be2, nullptr);
    gemm64<false, true, EPI_BIAS><<<dim3(1, 32), blk>>>(h2, Wmue, mu, BATCH, ZZ, HH, bmue, nullptr);

    for (int i = 0; i < 10; ++i) {
        gemm64<false, true, EPI_RELUB><<<dim3(8, 32), blk>>>(mu, Wd1, h1, BATCH, HH, ZZ, bd1, nullptr);
        gemm64<false, true, EPI_RELUB><<<dim3(8, 32), blk>>>(h1, Wd2, h2, BATCH, HH, HH, bd2, nullptr);
        gemm64<false, false, EPI_VEPI><<<dim3(8, 32), blk>>>(h2, G, v, BATCH, HH, HH, u, c);
        masked_mma<<<tgrid, blk>>>(Wd2, Wd1, h1, T1, 0);
        masked_mma<<<tgrid, blk>>>(G, T1, h2, GA2, HH * ZZ);
        iter_update<<<BATCH, 256>>>(dlv, 0.5f / (1.0f + (float)i));
    }

    gemm64<false, true, EPI_RELUB><<<dim3(8, 32), blk>>>(mu, Wd1, h1, BATCH, HH, ZZ, bd1, nullptr);
    gemm64<false, true, EPI_RELUB><<<dim3(8, 32), blk>>>(h1, Wd2, h2, BATCH, HH, HH, bd2, nullptr);
    masked_mma<<<tgrid, blk>>>(Wd2, Wd1, h1, T1, 0);
    masked_mma<<<tgrid, blk>>>(G, T1, h2, GA2, HH * ZZ);
    final_stats<<<BATCH, 256>>>(eps, dlv);

    gemm64<false, true, EPI_RELUB><<<dim3(8, 32), blk>>>(z, Wd1, h1, BATCH, HH, ZZ, bd1, nullptr);
    gemm64<false, true, EPI_RELUB><<<dim3(8, 32), blk>>>(h1, Wd2, h2, BATCH, HH, HH, bd2, nullptr);
    gemm64<false, true, EPI_BIAS><<<dim3(13, 32), blk>>>(h2, Wmu, T1, BATCH, DD, HH, bmu, nullptr);

    px_reduce<<<BATCH, 256>>>(x, T1, dlv);
    final_reduce<<<1, 256>>>(out);
}

// round 16
// speedup vs baseline: 2.4570x; 1.0626x over previous
#include <cuda_runtime.h>
#include <math.h>
#include <stdint.h>

#define BATCH 2048
#define DD 784
#define ZZ 32
#define HH 512
#define F_LOG2PI 1.8378770664093453f

// ---------------- scratch (device globals; no allocation allowed) ----------------
__device__ __align__(256) float g_G[HH * HH];
__device__ __align__(256) float g_c[HH];
__device__ __align__(256) float g_u[BATCH * HH];      // holds u - c after preamble
__device__ __align__(256) float g_h1[BATCH * HH];
__device__ __align__(256) float g_h2[BATCH * HH];
__device__ __align__(256) float g_mu[BATCH * ZZ];
__device__ __align__(256) float g_z[BATCH * ZZ];
__device__ __align__(256) float g_T1[(size_t)BATCH * HH * ZZ];   // reused as px_mu at end
__device__ __align__(256) float g_GA2[(size_t)BATCH * HH * ZZ];
__device__ __align__(256) float g_perb[BATCH];

enum { EPI_NONE = 0, EPI_BIAS = 1, EPI_RELUB = 2, EPI_SUBB = 3 };

// ---------------- packed f32x2 helpers (FFMA2) -----------------------------------
__device__ __forceinline__ unsigned long long pack2(float x) {
    unsigned long long d;
    asm("mov.b64 %0, {%1, %1};" : "=l"(d) : "f"(x));
    return d;
}
__device__ __forceinline__ void pack_from4(const float4& v,
                                           unsigned long long& p0,
                                           unsigned long long& p1) {
    asm("mov.b64 %0, {%1, %2};" : "=l"(p0) : "f"(v.x), "f"(v.y));
    asm("mov.b64 %0, {%1, %2};" : "=l"(p1) : "f"(v.z), "f"(v.w));
}
__device__ __forceinline__ void ffma2(unsigned long long& acc,
                                      unsigned long long a, unsigned long long b) {
    asm("fma.rn.f32x2 %0, %1, %2, %0;" : "+l"(acc) : "l"(a), "l"(b));
}
__device__ __forceinline__ float2 unpack2(unsigned long long d) {
    float lo, hi;
    asm("mov.b64 {%0, %1}, %2;" : "=f"(lo), "=f"(hi) : "l"(d));
    return make_float2(lo, hi);
}

// ---------------- tf32 helpers ----------------------------------------------------
__device__ __forceinline__ float tf32r(float f) {
    uint32_t r;
    asm("cvt.rna.tf32.f32 %0, %1;" : "=r"(r) : "f"(f));
    return __uint_as_float(r);
}
__device__ __forceinline__ void mma_tf32_16x8x8(float* c, const uint32_t* a,
                                                const uint32_t* b) {
    asm volatile(
        "mma.sync.aligned.m16n8k8.row.col.f32.tf32.tf32.f32 "
        "{%0,%1,%2,%3}, {%4,%5,%6,%7}, {%8,%9}, {%0,%1,%2,%3};"
        : "+f"(c[0]), "+f"(c[1]), "+f"(c[2]), "+f"(c[3])
        : "r"(a[0]), "r"(a[1]), "r"(a[2]), "r"(a[3]), "r"(b[0]), "r"(b[1]));
}

// ---------------- masked batched GEMM via mma.sync tf32 (hot kernel) -------------
// Out[b,i,z] = sum_j A[i,j] * (Hm[b,j]>0) * Bsrc[b*bstride + j*32 + z]
__global__ __launch_bounds__(256, 2)
void masked_mma(const float* __restrict__ A, const float* __restrict__ Bsrc,
                const float* __restrict__ Hm, float* __restrict__ Out, int bstride)
{
    __shared__ float As[2][16][136];
    __shared__ float Bs[2][4][16][40];

    const int t = threadIdx.x;
    const int w = t >> 5;
    const int lane = t & 31;
    const int rowBase = blockIdx.y * 128;
    const int b0 = blockIdx.x * 4;
    const int q = w >> 1;
    const int mh = (w & 1) * 64;

    float acc[4][4][4];
#pragma unroll
    for (int mt = 0; mt < 4; ++mt)
#pragma unroll
        for (int nt = 0; nt < 4; ++nt)
#pragma unroll
            for (int e = 0; e < 4; ++e) acc[mt][nt][e] = 0.f;

    const int g = lane >> 2;
    const int kt = lane & 3;

    auto load_chunk = [&](int c, int nb) {
        const int k0 = c * 16;
#pragma unroll
        for (int p = 0; p < 2; ++p) {
            int id = t + 256 * p;
            int m = id >> 2, kg = (id & 3) << 2;
            float4 v = *(const float4*)(A + (size_t)(rowBase + m) * HH + k0 + kg);
            As[nb][kg + 0][m] = tf32r(v.x);
            As[nb][kg + 1][m] = tf32r(v.y);
            As[nb][kg + 2][m] = tf32r(v.z);
            As[nb][kg + 3][m] = tf32r(v.w);
        }
#pragma unroll
        for (int p = 0; p < 2; ++p) {
            int id = t + 256 * p;
            int q2 = id >> 7, rem = id & 127;
            int k = rem >> 3, z4 = (rem & 7) << 2;
            const float* Bb = Bsrc + (size_t)(b0 + q2) * bstride;
            float4 v = *(const float4*)(Bb + (size_t)(k0 + k) * ZZ + z4);
            float msk = (Hm[(size_t)(b0 + q2) * HH + k0 + k] > 0.f) ? 1.f : 0.f;
            Bs[nb][q2][k][z4 + 0] = tf32r(v.x * msk);
            Bs[nb][q2][k][z4 + 1] = tf32r(v.y * msk);
            Bs[nb][q2][k][z4 + 2] = tf32r(v.z * msk);
            Bs[nb][q2][k][z4 + 3] = tf32r(v.w * msk);
        }
    };

    load_chunk(0, 0);
    __syncthreads();

    for (int c = 0; c < 32; ++c) {
        const int buf = c & 1;
        if (c < 31) load_chunk(c + 1, buf ^ 1);

#pragma unroll
        for (int ks = 0; ks < 2; ++ks) {
            const int kb = ks * 8;
            uint32_t af[4][4];
#pragma unroll
            for (int mt = 0; mt < 4; ++mt) {
                int m0 = mh + mt * 16;
                af[mt][0] = __float_as_uint(As[buf][kb + kt][m0 + g]);
                af[mt][1] = __float_as_uint(As[buf][kb + kt][m0 + 8 + g]);
                af[mt][2] = __float_as_uint(As[buf][kb + 4 + kt][m0 + g]);
                af[mt][3] = __float_as_uint(As[buf][kb + 4 + kt][m0 + 8 + g]);
            }
            uint32_t bf[4][2];
#pragma unroll
            for (int nt = 0; nt < 4; ++nt) {
                bf[nt][0] = __float_as_uint(Bs[buf][q][kb + kt][nt * 8 + g]);
                bf[nt][1] = __float_as_uint(Bs[buf][q][kb + 4 + kt][nt * 8 + g]);
            }
#pragma unroll
            for (int mt = 0; mt < 4; ++mt)
#pragma unroll
                for (int nt = 0; nt < 4; ++nt)
                    mma_tf32_16x8x8(acc[mt][nt], af[mt], bf[nt]);
        }
        __syncthreads();
    }

    float* Ob = Out + (size_t)(b0 + q) * (HH * ZZ);
#pragma unroll
    for (int mt = 0; mt < 4; ++mt) {
        int row = rowBase + mh + mt * 16 + g;
#pragma unroll
        for (int nt = 0; nt < 4; ++nt) {
            int col = nt * 8 + kt * 2;
            *(float2*)(Ob + (size_t)row * ZZ + col) =
                make_float2(acc[mt][nt][0], acc[mt][nt][1]);
            *(float2*)(Ob + (size_t)(row + 8) * ZZ + col) =
                make_float2(acc[mt][nt][2], acc[mt][nt][3]);
        }
    }
}

// ---------------- dense tf32 GEMM: C[M,N] = A[M,K] @ B[N,K]^T + epi --------------
// CTA tile 128x64, 8 warps of 32x32 (wm = w&3 m-quarter, wn = w>>2 n-half).
// M%128==0, K%16==0, N arbitrary (guarded). EPI_BIAS / EPI_RELUB.
template <int EPI>
__global__ __launch_bounds__(256, 2)
void gemm_tc(const float* __restrict__ A, const float* __restrict__ B,
             float* __restrict__ C, int M, int N, int K,
             const float* __restrict__ P0)
{
    __shared__ float As[2][16][136];
    __shared__ float Bs[2][16][72];

    const int t = threadIdx.x;
    const int w = t >> 5;
    const int lane = t & 31;
    const int rowBase = blockIdx.y * 128;
    const int colBase = blockIdx.x * 64;
    const int wm = w & 3;
    const int wn = w >> 2;
    const int g = lane >> 2;
    const int kt = lane & 3;

    float acc[2][4][4];
#pragma unroll
    for (int mt = 0; mt < 2; ++mt)
#pragma unroll
        for (int nt = 0; nt < 4; ++nt)
#pragma unroll
            for (int e = 0; e < 4; ++e) acc[mt][nt][e] = 0.f;

    auto load_chunk = [&](int c, int nb) {
        const int k0 = c * 16;
#pragma unroll
        for (int p = 0; p < 2; ++p) {
            int id = t + 256 * p;
            int m = id >> 2, kg = (id & 3) << 2;
            float4 v = *(const float4*)(A + (size_t)(rowBase + m) * K + k0 + kg);
            As[nb][kg + 0][m] = tf32r(v.x);
            As[nb][kg + 1][m] = tf32r(v.y);
            As[nb][kg + 2][m] = tf32r(v.z);
            As[nb][kg + 3][m] = tf32r(v.w);
        }
        {
            int n = t >> 2, kg = (t & 3) << 2;
            int gn = colBase + n;
            float4 v = make_float4(0.f, 0.f, 0.f, 0.f);
            if (gn < N) v = *(const float4*)(B + (size_t)gn * K + k0 + kg);
            Bs[nb][kg + 0][n] = tf32r(v.x);
            Bs[nb][kg + 1][n] = tf32r(v.y);
            Bs[nb][kg + 2][n] = tf32r(v.z);
            Bs[nb][kg + 3][n] = tf32r(v.w);
        }
    };

    const int nch = K / 16;
    load_chunk(0, 0);
    __syncthreads();

    for (int c = 0; c < nch; ++c) {
        const int buf = c & 1;
        if (c + 1 < nch) load_chunk(c + 1, buf ^ 1);

#pragma unroll
        for (int ks = 0; ks < 2; ++ks) {
            const int kb = ks * 8;
            uint32_t af[2][4];
#pragma unroll
            for (int mt = 0; mt < 2; ++mt) {
                int m0 = wm * 32 + mt * 16;
                af[mt][0] = __float_as_uint(As[buf][kb + kt][m0 + g]);
                af[mt][1] = __float_as_uint(As[buf][kb + kt][m0 + 8 + g]);
                af[mt][2] = __float_as_uint(As[buf][kb + 4 + kt][m0 + g]);
                af[mt][3] = __float_as_uint(As[buf][kb + 4 + kt][m0 + 8 + g]);
            }
            uint32_t bf[4][2];
#pragma unroll
            for (int nt = 0; nt < 4; ++nt) {
                int n0 = wn * 32 + nt * 8;
                bf[nt][0] = __float_as_uint(Bs[buf][kb + kt][n0 + g]);
                bf[nt][1] = __float_as_uint(Bs[buf][kb + 4 + kt][n0 + g]);
            }
#pragma unroll
            for (int mt = 0; mt < 2; ++mt)
#pragma unroll
                for (int nt = 0; nt < 4; ++nt)
                    mma_tf32_16x8x8(acc[mt][nt], af[mt], bf[nt]);
        }
        __syncthreads();
    }

#pragma unroll
    for (int mt = 0; mt < 2; ++mt) {
        int row = rowBase + wm * 32 + mt * 16 + g;
#pragma unroll
        for (int nt = 0; nt < 4; ++nt) {
            int col = colBase + wn * 32 + nt * 8 + kt * 2;
            if (col < N) {
                float b0v = (EPI == EPI_NONE) ? 0.f : P0[col];
                float b1v = (EPI == EPI_NONE) ? 0.f : P0[col + 1];
                float v0 = acc[mt][nt][0] + b0v;
                float v1 = acc[mt][nt][1] + b1v;
                float v2 = acc[mt][nt][2] + b0v;
                float v3 = acc[mt][nt][3] + b1v;
                if (EPI == EPI_RELUB) {
                    v0 = fmaxf(v0, 0.f); v1 = fmaxf(v1, 0.f);
                    v2 = fmaxf(v2, 0.f); v3 = fmaxf(v3, 0.f);
                }
                *(float2*)(C + (size_t)row * N + col)       = make_float2(v0, v1);
                *(float2*)(C + (size_t)(row + 8) * N + col) = make_float2(v2, v3);
            }
        }
    }
}

// ---------------- generic fp32 64x64 GEMM (preamble only) ------------------------
template <bool TA, bool TB, int EPI>
__global__ __launch_bounds__(256)
void gemm64(const float* __restrict__ A, const float* __restrict__ B,
            float* __restrict__ C, int M, int N, int K,
            const float* __restrict__ P0)
{
    __shared__ __align__(16) float As[16][64];
    __shared__ __align__(16) float Bs[16][64];
    const int t = threadIdx.x;
    const int rowBase = blockIdx.y * 64;
    const int colBase = blockIdx.x * 64;
    const int ty = t >> 4, tx = t & 15;

    unsigned long long acc[4][2] = {};

    for (int k0 = 0; k0 < K; k0 += 16) {
        if (!TA) {
            int r = t >> 2;
            int k4 = (t & 3) << 2;
            float4 v = *(const float4*)(A + (size_t)(rowBase + r) * K + k0 + k4);
            As[k4 + 0][r] = v.x; As[k4 + 1][r] = v.y;
            As[k4 + 2][r] = v.z; As[k4 + 3][r] = v.w;
        } else {
            int k = t >> 4;
            int m0 = (t & 15) << 2;
            *(float4*)(&As[k][m0]) =
                *(const float4*)(A + (size_t)(k0 + k) * M + rowBase + m0);
        }
        if (!TB) {
            int k = t >> 4;
            int n0 = (t & 15) << 2;
            int gn = colBase + n0;
            float4 v = make_float4(0.f, 0.f, 0.f, 0.f);
            if (gn < N) v = *(const float4*)(B + (size_t)(k0 + k) * N + gn);
            *(float4*)(&Bs[k][n0]) = v;
        } else {
            int n = t >> 2;
            int k4 = (t & 3) << 2;
            int gn = colBase + n;
            float4 v = make_float4(0.f, 0.f, 0.f, 0.f);
            if (gn < N) v = *(const float4*)(B + (size_t)gn * K + k0 + k4);
            Bs[k4 + 0][n] = v.x; Bs[k4 + 1][n] = v.y;
            Bs[k4 + 2][n] = v.z; Bs[k4 + 3][n] = v.w;
        }
        __syncthreads();
#pragma unroll
        for (int k = 0; k < 16; ++k) {
            float4 a = *(const float4*)(&As[k][ty << 2]);
            float4 b = *(const float4*)(&Bs[k][tx << 2]);
            unsigned long long bp[2];
            pack_from4(b, bp[0], bp[1]);
            unsigned long long ap[4];
            ap[0] = pack2(a.x); ap[1] = pack2(a.y);
            ap[2] = pack2(a.z); ap[3] = pack2(a.w);
#pragma unroll
            for (int i = 0; i < 4; ++i)
#pragma unroll
                for (int j = 0; j < 2; ++j)
                    ffma2(acc[i][j], ap[i], bp[j]);
        }
        __syncthreads();
    }
#pragma unroll
    for (int i = 0; i < 4; ++i) {
        int m = rowBase + (ty << 2) + i;
        float2 e0 = unpack2(acc[i][0]);
        float2 e1 = unpack2(acc[i][1]);
        float vals[4] = {e0.x, e0.y, e1.x, e1.y};
#pragma unroll
        for (int j = 0; j < 4; ++j) {
            int n = colBase + (tx << 2) + j;
            if (n < N) {
                float vv = vals[j];
                if (EPI == EPI_BIAS) vv += P0[n];
                else if (EPI == EPI_RELUB) vv = fmaxf(vv + P0[n], 0.f);
                else if (EPI == EPI_SUBB) vv -= P0[n];
                C[(size_t)m * N + n] = vv;
            }
        }
    }
}

// ---------------- per-batch iteration update -------------------------------------
// r1 = A2^T(u - c) - (GA2)^T h2 ; M = A2^T GA2 ; solve (vinv M + I) x = vinv(r1 + M mu)
__global__ __launch_bounds__(256)
void iter_update(const float* __restrict__ dlv, float alpha)
{
    const int b = blockIdx.x;
    const int t = threadIdx.x;
    __shared__ __align__(16) float A2s[64][32];
    __shared__ __align__(16) float G2s[64][32];
    __shared__ float ucs[64], h2s[64];
    __shared__ float Msh[32][33];
    __shared__ float Csh[32][33];
    __shared__ float r1[32], muS[32], rhs[32];

    const float* T1b = g_T1 + (size_t)b * (HH * ZZ);
    const float* G2b = g_GA2 + (size_t)b * (HH * ZZ);
    const float* h2b = g_h2 + (size_t)b * HH;
    const float* ub  = g_u + (size_t)b * HH;   // u - c

    float accM[4] = {0.f, 0.f, 0.f, 0.f};
    float accR = 0.f;

    for (int j0 = 0; j0 < HH; j0 += 64) {
        __syncthreads();
        for (int e = t * 4; e < 2048; e += 1024) {
            int j = e >> 5, z = e & 31;
            float m = (h2b[j0 + j] > 0.f) ? 1.f : 0.f;
            float4 a = *(const float4*)(T1b + (size_t)(j0 + j) * ZZ + z);
            a.x *= m; a.y *= m; a.z *= m; a.w *= m;
            *(float4*)(&A2s[j][z]) = a;
            *(float4*)(&G2s[j][z]) = *(const float4*)(G2b + (size_t)(j0 + j) * ZZ + z);
        }
        if (t < 64) { ucs[t] = ub[j0 + t]; h2s[t] = h2b[j0 + t]; }
        __syncthreads();
#pragma unroll
        for (int q = 0; q < 4; ++q) {
            int z1 = (t >> 5) + (q << 3);
            int z2 = t & 31;
            float s = 0.f;
#pragma unroll 16
            for (int j = 0; j < 64; ++j)
                s = fmaf(A2s[j][z1], G2s[j][z2], s);
            accM[q] += s;
        }
        if (t < 32) {
            float s = 0.f;
#pragma unroll 16
            for (int j = 0; j < 64; ++j) {
                s = fmaf(A2s[j][t], ucs[j], s);
                s = fmaf(-G2s[j][t], h2s[j], s);
            }
            accR += s;
        }
    }
    __syncthreads();
    {
        int z2 = t & 31;
        int r0 = t >> 5;
#pragma unroll
        for (int q = 0; q < 4; ++q) Msh[r0 + (q << 3)][z2] = accM[q];
    }
    if (t < 32) {
        r1[t]  = accR;
        muS[t] = g_mu[b * ZZ + t];
    }
    __syncthreads();

    if (t < 32) {
        const int lane = t;
        const float vinv = expf(-dlv[0]);
        float s = 0.f;
#pragma unroll
        for (int c = 0; c < 32; ++c) {
            Csh[lane][c] = vinv * Msh[lane][c] + ((lane == c) ? 1.f : 0.f);
            s = fmaf(Msh[lane][c], muS[c], s);
        }
        rhs[lane] = vinv * (r1[lane] + s);
        __syncwarp();
        for (int k = 0; k < 32; ++k) {
            if (lane == k) Csh[k][k] = sqrtf(Csh[k][k]);
            __syncwarp();
            float dk = Csh[k][k];
            if (lane > k) Csh[lane][k] /= dk;
            __syncwarp();
            if (lane > k) {
                float lk = Csh[lane][k];
                for (int c = k + 1; c <= lane; ++c)
                    Csh[lane][c] -= lk * Csh[c][k];
            }
            __syncwarp();
        }
        for (int k = 0; k < 32; ++k) {
            if (lane == k) rhs[k] /= Csh[k][k];
            __syncwarp();
            if (lane > k) rhs[lane] -= Csh[lane][k] * rhs[k];
            __syncwarp();
        }
        for (int k = 31; k >= 0; --k) {
            if (lane == k) rhs[k] /= Csh[k][k];
            __syncwarp();
            if (lane < k) rhs[lane] -= Csh[k][lane] * rhs[k];
            __syncwarp();
        }
        g_mu[b * ZZ + lane] = (1.f - alpha) * muS[lane] + alpha * rhs[lane];
    }
}

// ---------------- final per-batch: cov -> inv -> chol -> z, p_z - q_z ------------
__global__ __launch_bounds__(256)
void final_stats(const float* __restrict__ eps, const float* __restrict__ dlv)
{
    const int b = blockIdx.x;
    const int t = threadIdx.x;
    __shared__ __align__(16) float A2s[64][32];
    __shared__ __align__(16) float G2s[64][32];
    __shared__ float Msh[32][33];
    __shared__ float Csh[32][33];
    __shared__ float Xsh[32][33];
    __shared__ float Vsh[32][33];
    __shared__ float muS[32], epsS[32], dzS[32];

    const float* T1b = g_T1 + (size_t)b * (HH * ZZ);
    const float* G2b = g_GA2 + (size_t)b * (HH * ZZ);
    const float* h2b = g_h2 + (size_t)b * HH;

    float accM[4] = {0.f, 0.f, 0.f, 0.f};
    for (int j0 = 0; j0 < HH; j0 += 64) {
        __syncthreads();
        for (int e = t * 4; e < 2048; e += 1024) {
            int j = e >> 5, z = e & 31;
            float m = (h2b[j0 + j] > 0.f) ? 1.f : 0.f;
            float4 a = *(const float4*)(T1b + (size_t)(j0 + j) * ZZ + z);
            a.x *= m; a.y *= m; a.z *= m; a.w *= m;
            *(float4*)(&A2s[j][z]) = a;
            *(float4*)(&G2s[j][z]) = *(const float4*)(G2b + (size_t)(j0 + j) * ZZ + z);
        }
        __syncthreads();
#pragma unroll
        for (int q = 0; q < 4; ++q) {
            int z1 = (t >> 5) + (q << 3);
            int z2 = t & 31;
            float s = 0.f;
#pragma unroll 16
            for (int j = 0; j < 64; ++j)
                s = fmaf(A2s[j][z1], G2s[j][z2], s);
            accM[q] += s;
        }
    }
    __syncthreads();
    {
        int z2 = t & 31;
        int r0 = t >> 5;
#pragma unroll
        for (int q = 0; q < 4; ++q) Msh[r0 + (q << 3)][z2] = accM[q];
    }
    if (t < 32) {
        muS[t]  = g_mu[b * ZZ + t];
        epsS[t] = eps[b * ZZ + t];
    }
    __syncthreads();

    if (t < 32) {
        const int i = t;
        const float vinv = expf(-dlv[0]);
#pragma unroll
        for (int c = 0; c < 32; ++c)
            Csh[i][c] = vinv * Msh[i][c] + ((i == c) ? 1.f : 0.f);
        __syncwarp();
        for (int k = 0; k < 32; ++k) {
            if (i == k) Csh[k][k] = sqrtf(Csh[k][k]);
            __syncwarp();
            float dk = Csh[k][k];
            if (i > k) Csh[i][k] /= dk;
            __syncwarp();
            if (i > k) {
                float lk = Csh[i][k];
                for (int c = k + 1; c <= i; ++c)
                    Csh[i][c] -= lk * Csh[c][k];
            }
            __syncwarp();
        }
        for (int r = 0; r < 32; ++r) Xsh[r][i] = 0.f;
        __syncwarp();
        Xsh[i][i] = 1.f / Csh[i][i];
        for (int r = i + 1; r < 32; ++r) {
            float s = 0.f;
            for (int k = i; k < r; ++k) s = fmaf(Csh[r][k], Xsh[k][i], s);
            Xsh[r][i] = -s / Csh[r][r];
        }
        __syncwarp();
        for (int c = 0; c < 32; ++c) {
            float s = 0.f;
            int km = (i > c) ? i : c;
            for (int k = km; k < 32; ++k) s = fmaf(Xsh[k][i], Xsh[k][c], s);
            Vsh[i][c] = s;
        }
        __syncwarp();
        for (int k = 0; k < 32; ++k) {
            if (i == k) Vsh[k][k] = sqrtf(Vsh[k][k]);
            __syncwarp();
            float dk = Vsh[k][k];
            if (i > k) Vsh[i][k] /= dk;
            __syncwarp();
            if (i > k) {
                float lk = Vsh[i][k];
                for (int c = k + 1; c <= i; ++c)
                    Vsh[i][c] -= lk * Vsh[c][k];
            }
            __syncwarp();
        }
        float dz = 0.f;
        for (int c = 0; c <= i; ++c) dz = fmaf(Vsh[i][c], epsS[c], dz);
        float zi = muS[i] + dz;
        g_z[b * ZZ + i] = zi;
        dzS[i] = dz;
        __syncwarp();
        float cd = 0.f;
#pragma unroll
        for (int c = 0; c < 32; ++c)
            cd = fmaf(vinv * Msh[i][c] + ((i == c) ? 1.f : 0.f), dzS[c], cd);
        float qpart = dzS[i] * cd;
        float contrib = 0.5f * (F_LOG2PI + zi * zi)
                      + 0.5f * F_LOG2PI + logf(Vsh[i][i])
                      + 0.5f * qpart;
#pragma unroll
        for (int o = 16; o > 0; o >>= 1)
            contrib += __shfl_down_sync(0xffffffffu, contrib, o);
        if (i == 0) g_perb[b] = contrib;
    }
}

// ---------------- p_x reduction + final mean -------------------------------------
__global__ __launch_bounds__(256)
void px_reduce(const float* __restrict__ x, const float* __restrict__ pxmu,
               const float* __restrict__ dlv)
{
    const int b = blockIdx.x;
    const int t = threadIdx.x;
    const float dl = dlv[0];
    const float vinv = expf(-dl);
    float s = 0.f;
    for (int d = t; d < DD; d += 256) {
        float r = x[(size_t)b * DD + d] - pxmu[(size_t)b * DD + d];
        s += F_LOG2PI + dl + r * r * vinv;
    }
    __shared__ float sh[256];
    sh[t] = s; __syncthreads();
    for (int o = 128; o > 0; o >>= 1) {
        if (t < o) sh[t] += sh[t + o];
        __syncthreads();
    }
    if (t == 0) g_perb[b] += 0.5f * sh[0];
}

__global__ __launch_bounds__(256)
void final_reduce(float* __restrict__ out)
{
    const int t = threadIdx.x;
    float s = 0.f;
    for (int i = t; i < BATCH; i += 256) s += g_perb[i];
    __shared__ float sh[256];
    sh[t] = s; __syncthreads();
    for (int o = 128; o > 0; o >>= 1) {
        if (t < o) sh[t] += sh[t + o];
        __syncthreads();
    }
    if (t == 0) out[0] = -sh[0] / (float)BATCH;
}

__global__ void compute_c(const float* __restrict__ Wmu, const float* __restrict__ bmu,
                          float* __restrict__ c)
{
    int j = blockIdx.x * 256 + threadIdx.x;
    if (j < HH) {
        float s = 0.f;
        for (int d = 0; d < DD; ++d) s = fmaf(Wmu[(size_t)d * HH + j], bmu[d], s);
        c[j] = s;
    }
}

// ---------------- host orchestration ---------------------------------------------
extern "C" void kernel_launch(void* const* d_in, const int* in_sizes, int n_in,
                              void* d_out, int out_size)
{
    const float* x    = (const float*)d_in[0];
    const float* eps  = (const float*)d_in[1];
    const float* We1  = (const float*)d_in[2];
    const float* be1  = (const float*)d_in[3];
    const float* We2  = (const float*)d_in[4];
    const float* be2  = (const float*)d_in[5];
    const float* Wmue = (const float*)d_in[6];
    const float* bmue = (const float*)d_in[7];
    const float* Wd1  = (const float*)d_in[8];
    const float* bd1  = (const float*)d_in[9];
    const float* Wd2  = (const float*)d_in[10];
    const float* bd2  = (const float*)d_in[11];
    const float* Wmu  = (const float*)d_in[12];
    const float* bmu  = (const float*)d_in[13];
    const float* dlv  = (const float*)d_in[14];
    float* out = (float*)d_out;

    void *pG, *pc, *pu, *ph1, *ph2, *pmu, *pz, *pT1, *pGA2;
    cudaGetSymbolAddress(&pG, g_G);     cudaGetSymbolAddress(&pc, g_c);
    cudaGetSymbolAddress(&pu, g_u);     cudaGetSymbolAddress(&ph1, g_h1);
    cudaGetSymbolAddress(&ph2, g_h2);
    cudaGetSymbolAddress(&pmu, g_mu);   cudaGetSymbolAddress(&pz, g_z);
    cudaGetSymbolAddress(&pT1, g_T1);   cudaGetSymbolAddress(&pGA2, g_GA2);
    float *G = (float*)pG, *c = (float*)pc, *u = (float*)pu;
    float *h1 = (float*)ph1, *h2 = (float*)ph2;
    float *mu = (float*)pmu, *z = (float*)pz, *T1 = (float*)pT1, *GA2 = (float*)pGA2;

    dim3 blk(256);
    dim3 tgrid(BATCH / 4, HH / 128);       // masked_mma: 512 x 4
    dim3 dgridH(HH / 64, BATCH / 128);     // gemm_tc N=512: 8 x 16
    dim3 dgridZ(1, BATCH / 128);           // gemm_tc N=32
    dim3 dgridD(13, BATCH / 128);          // gemm_tc N=784 (13*64=832, guarded)

    // preamble (fp32): c, G = Wmu^T Wmu, uc = x@Wmu - c
    compute_c<<<2, 256>>>(Wmu, bmu, c);
    gemm64<true, false, EPI_NONE><<<dim3(8, 8), blk>>>(Wmu, Wmu, G, HH, HH, DD, nullptr);
    gemm64<false, false, EPI_SUBB><<<dim3(8, 32), blk>>>(x, Wmu, u, BATCH, HH, DD, c);

    // encoder (tf32)
    gemm_tc<EPI_RELUB><<<dgridH, blk>>>(x, We1, h1, BATCH, HH, DD, be1);
    gemm_tc<EPI_RELUB><<<dgridH, blk>>>(h1, We2, h2, BATCH, HH, HH, be2);
    gemm_tc<EPI_BIAS><<<dgridZ, blk>>>(h2, Wmue, mu, BATCH, ZZ, HH, bmue);

    for (int i = 0; i < 10; ++i) {
        gemm_tc<EPI_RELUB><<<dgridH, blk>>>(mu, Wd1, h1, BATCH, HH, ZZ, bd1);
        gemm_tc<EPI_RELUB><<<dgridH, blk>>>(h1, Wd2, h2, BATCH, HH, HH, bd2);
        masked_mma<<<tgrid, blk>>>(Wd2, Wd1, h1, T1, 0);
        masked_mma<<<tgrid, blk>>>(G, T1, h2, GA2, HH * ZZ);
        iter_update<<<BATCH, 256>>>(dlv, 0.5f / (1.0f + (float)i));
    }

    gemm_tc<EPI_RELUB><<<dgridH, blk>>>(mu, Wd1, h1, BATCH, HH, ZZ, bd1);
    gemm_tc<EPI_RELUB><<<dgridH, blk>>>(h1, Wd2, h2, BATCH, HH, HH, bd2);
    masked_mma<<<tgrid, blk>>>(Wd2, Wd1, h1, T1, 0);
    masked_mma<<<tgrid, blk>>>(G, T1, h2, GA2, HH * ZZ);
    final_stats<<<BATCH, 256>>>(eps, dlv);

    gemm_tc<EPI_RELUB><<<dgridH, blk>>>(z, Wd1, h1, BATCH, HH, ZZ, bd1);
    gemm_tc<EPI_RELUB><<<dgridH, blk>>>(h1, Wd2, h2, BATCH, HH, HH, bd2);
    gemm_tc<EPI_BIAS><<<dgridD, blk>>>(h2, Wmu, T1, BATCH, DD, HH, bmu);

    px_reduce<<<BATCH, 256>>>(x, T1, dlv);
    final_reduce<<<1, 256>>>(out);
}